// round 1
// baseline (speedup 1.0000x reference)
#include <cuda_runtime.h>

#define Bc 8
#define Sc 384
#define Dc 1024
#define Hc 16
#define HDc 64
#define D3c 3072
#define BSc 3072   // B*S

// Scratch (static device globals; no runtime allocation)
__device__ float g_qkv[(size_t)BSc * D3c];            // 37.7 MB: qkv projection
__device__ float g_vals[(size_t)BSc * Dc];            // 12.6 MB: attention @ V, (b,s,d) layout
__device__ float g_attn[(size_t)Bc * Hc * Sc * Sc];   // 75.5 MB: fallback if out buffer lacks attn region

// ---------------------------------------------------------------------------
// Generic fp32 GEMM: C[M,N] = A[M,K] @ B[K,N] + bias[N]
// 128x128 tile, BK=8, 256 threads, 8x8 per-thread register tile.
// Requires M%128==0, N%128==0, K%8==0 (true for all uses here).
// ---------------------------------------------------------------------------
__global__ __launch_bounds__(256) void sgemm_bias_kernel(
    const float* __restrict__ A, const float* __restrict__ Bm,
    const float* __restrict__ bias, float* __restrict__ C,
    int M, int N, int K)
{
    __shared__ float As[8][128];
    __shared__ float Bs[8][128];
    const int tid = threadIdx.x;
    const int bm = blockIdx.y * 128;
    const int bn = blockIdx.x * 128;
    const int lr = tid >> 1;          // A tile row 0..127
    const int lc = (tid & 1) * 4;     // A tile k-offset 0/4
    const int br = tid >> 5;          // B tile k-row 0..7
    const int bc = (tid & 31) * 4;    // B tile col 0..124
    const int tr = (tid >> 4) * 8;
    const int tc = (tid & 15) * 8;
    float acc[8][8] = {};

    const float* Aptr = A + (size_t)(bm + lr) * K + lc;
    const float* Bptr = Bm + (size_t)br * N + bn + bc;

    for (int k0 = 0; k0 < K; k0 += 8) {
        float4 av = *(const float4*)(Aptr + k0);
        As[lc + 0][lr] = av.x; As[lc + 1][lr] = av.y;
        As[lc + 2][lr] = av.z; As[lc + 3][lr] = av.w;
        float4 bv = *(const float4*)(Bptr + (size_t)k0 * N);
        *(float4*)&Bs[br][bc] = bv;
        __syncthreads();
        #pragma unroll
        for (int kk = 0; kk < 8; kk++) {
            float ar[8], brg[8];
            #pragma unroll
            for (int u = 0; u < 8; u++) ar[u] = As[kk][tr + u];
            #pragma unroll
            for (int u = 0; u < 8; u++) brg[u] = Bs[kk][tc + u];
            #pragma unroll
            for (int i = 0; i < 8; i++)
                #pragma unroll
                for (int j = 0; j < 8; j++)
                    acc[i][j] = fmaf(ar[i], brg[j], acc[i][j]);
        }
        __syncthreads();
    }
    #pragma unroll
    for (int i = 0; i < 8; i++) {
        float* crow = C + (size_t)(bm + tr + i) * N + bn + tc;
        #pragma unroll
        for (int j = 0; j < 8; j += 4) {
            float4 o;
            o.x = acc[i][j + 0] + bias[bn + tc + j + 0];
            o.y = acc[i][j + 1] + bias[bn + tc + j + 1];
            o.z = acc[i][j + 2] + bias[bn + tc + j + 2];
            o.w = acc[i][j + 3] + bias[bn + tc + j + 3];
            *(float4*)(crow + j) = o;
        }
    }
}

// ---------------------------------------------------------------------------
// logits[b,h,i,j] = scale * sum_dd q[b,h,i,dd] * k[b,h,j,dd]
// grid: (S/128, S/128, B*H), 128x128 tile over (i,j), K=64.
// ---------------------------------------------------------------------------
__global__ __launch_bounds__(256) void qk_kernel(
    const float* __restrict__ qkv, float* __restrict__ attn)
{
    const int bh = blockIdx.z;
    const int b = bh >> 4, h = bh & 15;
    const float* qbase = qkv + (size_t)(b * Sc) * D3c + h * 192;
    const float* kbase = qbase + 64;
    const int i0 = blockIdx.y * 128, j0 = blockIdx.x * 128;
    __shared__ float Qs[8][128], Ks[8][128];
    const int tid = threadIdx.x;
    const int lr = tid >> 1;
    const int lc = (tid & 1) * 4;
    const int tr = (tid >> 4) * 8;
    const int tc = (tid & 15) * 8;
    float acc[8][8] = {};
    for (int k0 = 0; k0 < HDc; k0 += 8) {
        float4 qv = *(const float4*)&qbase[(size_t)(i0 + lr) * D3c + k0 + lc];
        Qs[lc + 0][lr] = qv.x; Qs[lc + 1][lr] = qv.y;
        Qs[lc + 2][lr] = qv.z; Qs[lc + 3][lr] = qv.w;
        float4 kv = *(const float4*)&kbase[(size_t)(j0 + lr) * D3c + k0 + lc];
        Ks[lc + 0][lr] = kv.x; Ks[lc + 1][lr] = kv.y;
        Ks[lc + 2][lr] = kv.z; Ks[lc + 3][lr] = kv.w;
        __syncthreads();
        #pragma unroll
        for (int kk = 0; kk < 8; kk++) {
            float qr[8], kr[8];
            #pragma unroll
            for (int u = 0; u < 8; u++) qr[u] = Qs[kk][tr + u];
            #pragma unroll
            for (int u = 0; u < 8; u++) kr[u] = Ks[kk][tc + u];
            #pragma unroll
            for (int i = 0; i < 8; i++)
                #pragma unroll
                for (int j = 0; j < 8; j++)
                    acc[i][j] = fmaf(qr[i], kr[j], acc[i][j]);
        }
        __syncthreads();
    }
    const float scale = 0.125f;  // 1/sqrt(64)
    float* obase = attn + (size_t)bh * Sc * Sc;
    #pragma unroll
    for (int i = 0; i < 8; i++) {
        float* orow = obase + (size_t)(i0 + tr + i) * Sc + j0 + tc;
        #pragma unroll
        for (int j = 0; j < 8; j += 4) {
            float4 o = make_float4(acc[i][j] * scale, acc[i][j + 1] * scale,
                                   acc[i][j + 2] * scale, acc[i][j + 3] * scale);
            *(float4*)(orow + j) = o;
        }
    }
}

// ---------------------------------------------------------------------------
// XL relative bias. Derivation of the raw reshape:
//   rpem[h,i,j,dd] = rpe_flat[r0(h,i)*1024 + 64*j + dd],
//   r0 = 384 + 24*(i&15) - 24*h - (i>>4)      (contiguous slab per (h,i)!)
// attn[b,h,i,j] += q[b,h,i,:] . rpe_flat[r0*1024 + 64*j : +64]
// One block per (h,i); all 8 batches share the slab.
// ---------------------------------------------------------------------------
__global__ __launch_bounds__(128) void rpe_bias_kernel(
    const float* __restrict__ qkv, const float* __restrict__ rpe,
    float* __restrict__ attn)
{
    const int h = blockIdx.x / Sc;
    const int i = blockIdx.x % Sc;
    const int r0 = 384 + 24 * (i & 15) - 24 * h - (i >> 4);
    const float* rbase = rpe + (size_t)r0 * 1024;
    __shared__ float Qs[Bc][HDc];
    const int tid = threadIdx.x;
    for (int t = tid; t < Bc * HDc; t += 128) {
        int b = t >> 6, dd = t & 63;
        Qs[b][dd] = qkv[(size_t)(b * Sc + i) * D3c + h * 192 + dd];
    }
    __syncthreads();

    float acc[3][Bc];
    #pragma unroll
    for (int jj = 0; jj < 3; jj++)
        #pragma unroll
        for (int b = 0; b < Bc; b++) acc[jj][b] = 0.f;

    #pragma unroll
    for (int c = 0; c < 16; c++) {
        float4 qv[Bc];
        #pragma unroll
        for (int b = 0; b < Bc; b++) qv[b] = *(const float4*)&Qs[b][c * 4];
        #pragma unroll
        for (int jj = 0; jj < 3; jj++) {
            int j = tid + jj * 128;
            float4 rv = *(const float4*)(rbase + (size_t)j * 64 + c * 4);
            #pragma unroll
            for (int b = 0; b < Bc; b++)
                acc[jj][b] += qv[b].x * rv.x + qv[b].y * rv.y +
                              qv[b].z * rv.z + qv[b].w * rv.w;
        }
    }
    #pragma unroll
    for (int jj = 0; jj < 3; jj++) {
        int j = tid + jj * 128;
        #pragma unroll
        for (int b = 0; b < Bc; b++) {
            size_t idx = ((size_t)(b * Hc + h) * Sc + i) * Sc + j;
            attn[idx] += acc[jj][b];
        }
    }
}

// ---------------------------------------------------------------------------
// In-place row softmax over last dim (S=384). One block of 128 per row.
// ---------------------------------------------------------------------------
__global__ __launch_bounds__(128) void softmax_kernel(float* __restrict__ attn)
{
    float* p = attn + (size_t)blockIdx.x * Sc;
    const int tid = threadIdx.x;
    float v[3];
    float m = -1e30f;
    #pragma unroll
    for (int c = 0; c < 3; c++) { v[c] = p[tid + c * 128]; m = fmaxf(m, v[c]); }
    #pragma unroll
    for (int o = 16; o > 0; o >>= 1) m = fmaxf(m, __shfl_xor_sync(0xffffffffu, m, o));
    __shared__ float red[4];
    if ((tid & 31) == 0) red[tid >> 5] = m;
    __syncthreads();
    m = fmaxf(fmaxf(red[0], red[1]), fmaxf(red[2], red[3]));
    __syncthreads();
    float s = 0.f;
    #pragma unroll
    for (int c = 0; c < 3; c++) { v[c] = __expf(v[c] - m); s += v[c]; }
    #pragma unroll
    for (int o = 16; o > 0; o >>= 1) s += __shfl_xor_sync(0xffffffffu, s, o);
    if ((tid & 31) == 0) red[tid >> 5] = s;
    __syncthreads();
    s = red[0] + red[1] + red[2] + red[3];
    const float inv = 1.0f / s;
    #pragma unroll
    for (int c = 0; c < 3; c++) p[tid + c * 128] = v[c] * inv;
}

// ---------------------------------------------------------------------------
// values[b,i,h*64+dd] = sum_j attn[b,h,i,j] * v[b,h,j,dd]
// grid: (1, S/128, B*H); 128x64 output tile, BK=16.
// ---------------------------------------------------------------------------
__global__ __launch_bounds__(256) void av_kernel(
    const float* __restrict__ attn, const float* __restrict__ qkv,
    float* __restrict__ vals)
{
    const int bh = blockIdx.z;
    const int b = bh >> 4, h = bh & 15;
    const int i0 = blockIdx.y * 128;
    const float* abase = attn + ((size_t)bh * Sc + i0) * Sc;
    const float* vbase = qkv + (size_t)(b * Sc) * D3c + h * 192 + 128;
    __shared__ float As[16][128];
    __shared__ float Vs[16][64];
    const int tid = threadIdx.x;
    const int ar = tid >> 1;
    const int ac = (tid & 1) * 8;
    const int vr = tid >> 4;
    const int vc = (tid & 15) * 4;
    const int tr = (tid >> 4) * 8;
    const int tc = (tid & 15) * 4;
    float acc[8][4] = {};
    for (int j0 = 0; j0 < Sc; j0 += 16) {
        float4 a0 = *(const float4*)&abase[(size_t)ar * Sc + j0 + ac];
        float4 a1 = *(const float4*)&abase[(size_t)ar * Sc + j0 + ac + 4];
        As[ac + 0][ar] = a0.x; As[ac + 1][ar] = a0.y;
        As[ac + 2][ar] = a0.z; As[ac + 3][ar] = a0.w;
        As[ac + 4][ar] = a1.x; As[ac + 5][ar] = a1.y;
        As[ac + 6][ar] = a1.z; As[ac + 7][ar] = a1.w;
        *(float4*)&Vs[vr][vc] = *(const float4*)&vbase[(size_t)(j0 + vr) * D3c + vc];
        __syncthreads();
        #pragma unroll
        for (int kk = 0; kk < 16; kk++) {
            float arg[8], vrg[4];
            #pragma unroll
            for (int u = 0; u < 8; u++) arg[u] = As[kk][tr + u];
            #pragma unroll
            for (int u = 0; u < 4; u++) vrg[u] = Vs[kk][tc + u];
            #pragma unroll
            for (int i = 0; i < 8; i++)
                #pragma unroll
                for (int j = 0; j < 4; j++)
                    acc[i][j] = fmaf(arg[i], vrg[j], acc[i][j]);
        }
        __syncthreads();
    }
    #pragma unroll
    for (int i = 0; i < 8; i++) {
        float4 o = make_float4(acc[i][0], acc[i][1], acc[i][2], acc[i][3]);
        *(float4*)&vals[(size_t)(b * Sc + i0 + tr + i) * Dc + h * 64 + tc] = o;
    }
}

// ---------------------------------------------------------------------------
extern "C" void kernel_launch(void* const* d_in, const int* in_sizes, int n_in,
                              void* d_out, int out_size)
{
    const float* x     = (const float*)d_in[0];
    const float* qkv_w = (const float*)d_in[1];
    const float* qkv_b = (const float*)d_in[2];
    const float* out_w = (const float*)d_in[3];
    const float* out_b = (const float*)d_in[4];
    const float* rpe   = (const float*)d_in[5];

    float *qkvbuf = nullptr, *valsbuf = nullptr, *attnscr = nullptr;
    cudaGetSymbolAddress((void**)&qkvbuf, g_qkv);
    cudaGetSymbolAddress((void**)&valsbuf, g_vals);
    cudaGetSymbolAddress((void**)&attnscr, g_attn);

    float* out = (float*)d_out;
    const long OUT_E = (long)BSc * Dc;            // 3,145,728
    const long ATT_E = (long)Bc * Hc * Sc * Sc;   // 18,874,368
    float* attn = ((long)out_size >= OUT_E + ATT_E) ? (out + OUT_E) : attnscr;

    // 1) qkv = x @ qkv_w + qkv_b
    sgemm_bias_kernel<<<dim3(24, 24), 256>>>(x, qkv_w, qkv_b, qkvbuf, BSc, D3c, Dc);
    // 2) logits = scale * q k^T
    qk_kernel<<<dim3(3, 3, Bc * Hc), 256>>>(qkvbuf, attn);
    // 3) logits += q . rpem  (contiguous-slab formulation)
    rpe_bias_kernel<<<Hc * Sc, 128>>>(qkvbuf, rpe, attn);
    // 4) softmax rows
    softmax_kernel<<<Bc * Hc * Sc, 128>>>(attn);
    // 5) values = attn @ v  (written in (b,s,d) layout)
    av_kernel<<<dim3(1, 3, Bc * Hc), 256>>>(attn, qkvbuf, valsbuf);
    // 6) out = values @ out_w + out_b
    sgemm_bias_kernel<<<dim3(8, 24), 256>>>(valsbuf, out_w, out_b, out, BSc, Dc, Dc);
}

// round 3
// speedup vs baseline: 1.4799x; 1.4799x over previous
#include <cuda_runtime.h>
#include <cuda_bf16.h>
#include <cstdint>

#define Bc 8
#define Sc 384
#define Dc 1024
#define Hc 16
#define HDc 64
#define D3c 3072
#define BSc 3072   // B*S

// ---------------------------------------------------------------------------
// Scratch (static device globals; no runtime allocation)
// ---------------------------------------------------------------------------
__device__ float g_qkv[(size_t)BSc * D3c];            // qkv projection (fp32)
__device__ float g_vals[(size_t)BSc * Dc];            // attn @ V, (b,s,d)
__device__ float g_attn[(size_t)Bc * Hc * Sc * Sc];   // fallback attn buffer
__device__ __align__(16) __nv_bfloat16 g_ah[(size_t)BSc * Dc];   // A hi (x, then vals)
__device__ __align__(16) __nv_bfloat16 g_al[(size_t)BSc * Dc];   // A lo
__device__ __align__(16) __nv_bfloat16 g_wqh[(size_t)D3c * Dc];  // qkv_w^T hi [N,K]
__device__ __align__(16) __nv_bfloat16 g_wql[(size_t)D3c * Dc];  // qkv_w^T lo
__device__ __align__(16) __nv_bfloat16 g_woh[(size_t)Dc * Dc];   // out_w^T hi
__device__ __align__(16) __nv_bfloat16 g_wol[(size_t)Dc * Dc];   // out_w^T lo

// ---------------------------------------------------------------------------
// Baseline-PTX tensor-core helpers (sm_80+ ISA; valid for compute_103)
// ---------------------------------------------------------------------------
__device__ __forceinline__ uint32_t smem_u32(const void* p) {
    uint32_t a;
    asm("{ .reg .u64 t; cvta.to.shared.u64 t, %1; cvt.u32.u64 %0, t; }" : "=r"(a) : "l"(p));
    return a;
}
#define CP_ASYNC16(sm, gp) \
    asm volatile("cp.async.cg.shared.global [%0], [%1], 16;" :: "r"(sm), "l"(gp))
#define CP_COMMIT() asm volatile("cp.async.commit_group;" ::: "memory")
#define CP_WAIT1()  asm volatile("cp.async.wait_group 1;" ::: "memory")

#define LDSM_X4(r, a) \
    asm volatile("ldmatrix.sync.aligned.m8n8.x4.shared.b16 {%0,%1,%2,%3}, [%4];" \
        : "=r"((r)[0]), "=r"((r)[1]), "=r"((r)[2]), "=r"((r)[3]) : "r"(a))

__device__ __forceinline__ void mma_bf16(float* d, const uint32_t* a,
                                         uint32_t b0, uint32_t b1) {
    asm volatile(
        "mma.sync.aligned.m16n8k16.row.col.f32.bf16.bf16.f32 "
        "{%0,%1,%2,%3}, {%4,%5,%6,%7}, {%8,%9}, {%0,%1,%2,%3};"
        : "+f"(d[0]), "+f"(d[1]), "+f"(d[2]), "+f"(d[3])
        : "r"(a[0]), "r"(a[1]), "r"(a[2]), "r"(a[3]), "r"(b0), "r"(b1));
}

// ---------------------------------------------------------------------------
// HMMA bf16-split GEMM: C[M,N] = (Ah+Al)[M,K] @ (Bh+Bl)[N,K]^T + bias
//   3-pass: Ah*Bh + Al*Bh + Ah*Bl, fp32 register accumulation.
// CTA 128x128, 8 warps (warp tile 64x32), K-chunk 32, double-buffered cp.async.
// SMEM tile layout: 128 rows x 64B, swizzle slot = c ^ ((row>>1)&3), c = k16B-chunk.
// ---------------------------------------------------------------------------
#define TILE_B 8192                 // one 128x32 bf16 tile
#define BUF_B  (4 * TILE_B)         // Ah,Al,Bh,Bl
#define GSMEM  (2 * BUF_B)          // 64 KB double buffer

__global__ __launch_bounds__(256, 1) void mma_gemm_kernel(
    const __nv_bfloat16* __restrict__ Ah, const __nv_bfloat16* __restrict__ Al,
    const __nv_bfloat16* __restrict__ Bh, const __nv_bfloat16* __restrict__ Bl,
    const float* __restrict__ bias, float* __restrict__ C,
    int M, int N, int K)
{
    extern __shared__ char smem[];
    const uint32_t sbase = smem_u32(smem);
    const int tid  = threadIdx.x;
    const int wid  = tid >> 5;
    const int lane = tid & 31;
    const int m0 = blockIdx.y * 128;
    const int n0 = blockIdx.x * 128;
    const int mw = (wid & 1) * 64;     // warp m offset
    const int nw = (wid >> 1) * 32;    // warp n offset

    // ---- cp.async source/dest mapping: row = tid>>1, chunks c0=(tid&1)*2, c0+1
    const int lrow = tid >> 1;
    const int c0   = (tid & 1) * 2;
    const int sw0  = (lrow >> 1) & 3;
    const __nv_bfloat16* gAh = Ah + (size_t)(m0 + lrow) * K;
    const __nv_bfloat16* gAl = Al + (size_t)(m0 + lrow) * K;
    const __nv_bfloat16* gBh = Bh + (size_t)(n0 + lrow) * K;
    const __nv_bfloat16* gBl = Bl + (size_t)(n0 + lrow) * K;
    const uint32_t soff0 = lrow * 64 + (((c0 + 0) ^ sw0) << 4);
    const uint32_t soff1 = lrow * 64 + (((c0 + 1) ^ sw0) << 4);

    const int NK = K >> 5;  // 32-wide K chunks

    auto issue = [&](int it) {
        if (it < NK) {
            const uint32_t tb = sbase + (it & 1) * BUF_B;
            const int k0 = it << 5;
            CP_ASYNC16(tb + 0 * TILE_B + soff0, gAh + k0 + (c0 + 0) * 8);
            CP_ASYNC16(tb + 0 * TILE_B + soff1, gAh + k0 + (c0 + 1) * 8);
            CP_ASYNC16(tb + 1 * TILE_B + soff0, gAl + k0 + (c0 + 0) * 8);
            CP_ASYNC16(tb + 1 * TILE_B + soff1, gAl + k0 + (c0 + 1) * 8);
            CP_ASYNC16(tb + 2 * TILE_B + soff0, gBh + k0 + (c0 + 0) * 8);
            CP_ASYNC16(tb + 2 * TILE_B + soff1, gBh + k0 + (c0 + 1) * 8);
            CP_ASYNC16(tb + 3 * TILE_B + soff0, gBl + k0 + (c0 + 0) * 8);
            CP_ASYNC16(tb + 3 * TILE_B + soff1, gBl + k0 + (c0 + 1) * 8);
        }
        CP_COMMIT();
    };

    // ---- ldmatrix per-thread base addresses (ks=0); ks=1 = XOR 32
    // A/B tiles share the same addressing: row = base + (lane&15), c0 = lane>>4
    const int frow = lane & 15;
    const int fc   = lane >> 4;
    auto fr_addr = [&](int rbase) -> uint32_t {
        const int row = rbase + frow;
        return (uint32_t)(row * 64 + ((fc ^ ((row >> 1) & 3)) << 4));
    };
    // A m-tiles: rows mw + mt*16 ; since mt*16 doesn't change (row>>1)&3, +1024/mt
    const uint32_t aoff = fr_addr(mw);
    const uint32_t boff = fr_addr(nw);

    float acc[4][4][4];
    #pragma unroll
    for (int i = 0; i < 4; i++)
        #pragma unroll
        for (int j = 0; j < 4; j++)
            #pragma unroll
            for (int r = 0; r < 4; r++) acc[i][j][r] = 0.f;

    issue(0);
    issue(1);

    for (int it = 0; it < NK; it++) {
        CP_WAIT1();
        __syncthreads();
        const uint32_t tb = sbase + (it & 1) * BUF_B;
        #pragma unroll
        for (int ks = 0; ks < 2; ks++) {
            const uint32_t kx = ks ? 32u : 0u;
            uint32_t ah[4][4], al4[4][4], bh[2][4], bl4[2][4];
            #pragma unroll
            for (int mt = 0; mt < 4; mt++) {
                LDSM_X4(ah[mt],  tb + 0 * TILE_B + ((aoff + mt * 1024) ^ kx));
                LDSM_X4(al4[mt], tb + 1 * TILE_B + ((aoff + mt * 1024) ^ kx));
            }
            #pragma unroll
            for (int bt = 0; bt < 2; bt++) {
                LDSM_X4(bh[bt],  tb + 2 * TILE_B + ((boff + bt * 1024) ^ kx));
                LDSM_X4(bl4[bt], tb + 3 * TILE_B + ((boff + bt * 1024) ^ kx));
            }
            #pragma unroll
            for (int mt = 0; mt < 4; mt++) {
                #pragma unroll
                for (int nt = 0; nt < 4; nt++) {
                    const int bt = nt >> 1, hf = nt & 1;
                    const uint32_t b0h = bh[bt][hf], b1h = bh[bt][hf + 2];
                    const uint32_t b0l = bl4[bt][hf], b1l = bl4[bt][hf + 2];
                    mma_bf16(acc[mt][nt], ah[mt],  b0h, b1h);
                    mma_bf16(acc[mt][nt], al4[mt], b0h, b1h);
                    mma_bf16(acc[mt][nt], ah[mt],  b0l, b1l);
                }
            }
        }
        __syncthreads();
        issue(it + 2);
    }

    // ---- epilogue: D frag (16x8): c0,c1 -> (row=l/4, col=2*(l&3)); c2,c3 -> row+8
    const int er = lane >> 2;
    const int ec = (lane & 3) * 2;
    #pragma unroll
    for (int mt = 0; mt < 4; mt++) {
        #pragma unroll
        for (int nt = 0; nt < 4; nt++) {
            const int col = n0 + nw + nt * 8 + ec;
            const float bx = __ldg(&bias[col]);
            const float by = __ldg(&bias[col + 1]);
            const int r0 = m0 + mw + mt * 16 + er;
            float2 v0 = make_float2(acc[mt][nt][0] + bx, acc[mt][nt][1] + by);
            float2 v1 = make_float2(acc[mt][nt][2] + bx, acc[mt][nt][3] + by);
            *(float2*)(C + (size_t)r0 * N + col) = v0;
            *(float2*)(C + (size_t)(r0 + 8) * N + col) = v1;
        }
    }
}

// ---------------------------------------------------------------------------
// fp32 -> bf16 hi/lo split (vectorized by 4)
// ---------------------------------------------------------------------------
__global__ __launch_bounds__(256) void split_kernel(
    const float* __restrict__ src, __nv_bfloat16* __restrict__ hi,
    __nv_bfloat16* __restrict__ lo, int n4)
{
    int i = blockIdx.x * blockDim.x + threadIdx.x;
    if (i >= n4) return;
    float4 v = ((const float4*)src)[i];
    __nv_bfloat16 h0 = __float2bfloat16(v.x), h1 = __float2bfloat16(v.y);
    __nv_bfloat16 h2 = __float2bfloat16(v.z), h3 = __float2bfloat16(v.w);
    __nv_bfloat16 l0 = __float2bfloat16(v.x - __bfloat162float(h0));
    __nv_bfloat16 l1 = __float2bfloat16(v.y - __bfloat162float(h1));
    __nv_bfloat16 l2 = __float2bfloat16(v.z - __bfloat162float(h2));
    __nv_bfloat16 l3 = __float2bfloat16(v.w - __bfloat162float(h3));
    ((__nv_bfloat162*)hi)[2 * i]     = __nv_bfloat162(h0, h1);
    ((__nv_bfloat162*)hi)[2 * i + 1] = __nv_bfloat162(h2, h3);
    ((__nv_bfloat162*)lo)[2 * i]     = __nv_bfloat162(l0, l1);
    ((__nv_bfloat162*)lo)[2 * i + 1] = __nv_bfloat162(l2, l3);
}

// ---------------------------------------------------------------------------
// W[K,N] -> Wt[N,K] with bf16 hi/lo split (32x32 smem tile transpose)
// ---------------------------------------------------------------------------
__global__ __launch_bounds__(256) void transpose_split_kernel(
    const float* __restrict__ W, __nv_bfloat16* __restrict__ Th,
    __nv_bfloat16* __restrict__ Tl, int K, int N)
{
    __shared__ float t[32][33];
    const int n0 = blockIdx.x * 32, k0 = blockIdx.y * 32;
    const int tx = threadIdx.x, ty = threadIdx.y;
    #pragma unroll
    for (int r = 0; r < 4; r++)
        t[ty + 8 * r][tx] = W[(size_t)(k0 + ty + 8 * r) * N + n0 + tx];
    __syncthreads();
    #pragma unroll
    for (int r = 0; r < 4; r++) {
        float v = t[tx][ty + 8 * r];
        __nv_bfloat16 h = __float2bfloat16(v);
        __nv_bfloat16 l = __float2bfloat16(v - __bfloat162float(h));
        size_t o = (size_t)(n0 + ty + 8 * r) * K + k0 + tx;
        Th[o] = h; Tl[o] = l;
    }
}

// ---------------------------------------------------------------------------
// logits[b,h,i,j] = scale * q . k   (fp32 SIMT)
// ---------------------------------------------------------------------------
__global__ __launch_bounds__(256) void qk_kernel(
    const float* __restrict__ qkv, float* __restrict__ attn)
{
    const int bh = blockIdx.z;
    const int b = bh >> 4, h = bh & 15;
    const float* qbase = qkv + (size_t)(b * Sc) * D3c + h * 192;
    const float* kbase = qbase + 64;
    const int i0 = blockIdx.y * 128, j0 = blockIdx.x * 128;
    __shared__ float Qs[8][128], Ks[8][128];
    const int tid = threadIdx.x;
    const int lr = tid >> 1;
    const int lc = (tid & 1) * 4;
    const int tr = (tid >> 4) * 8;
    const int tc = (tid & 15) * 8;
    float acc[8][8] = {};
    for (int k0 = 0; k0 < HDc; k0 += 8) {
        float4 qv = *(const float4*)&qbase[(size_t)(i0 + lr) * D3c + k0 + lc];
        Qs[lc + 0][lr] = qv.x; Qs[lc + 1][lr] = qv.y;
        Qs[lc + 2][lr] = qv.z; Qs[lc + 3][lr] = qv.w;
        float4 kv = *(const float4*)&kbase[(size_t)(j0 + lr) * D3c + k0 + lc];
        Ks[lc + 0][lr] = kv.x; Ks[lc + 1][lr] = kv.y;
        Ks[lc + 2][lr] = kv.z; Ks[lc + 3][lr] = kv.w;
        __syncthreads();
        #pragma unroll
        for (int kk = 0; kk < 8; kk++) {
            float qr[8], kr[8];
            #pragma unroll
            for (int u = 0; u < 8; u++) qr[u] = Qs[kk][tr + u];
            #pragma unroll
            for (int u = 0; u < 8; u++) kr[u] = Ks[kk][tc + u];
            #pragma unroll
            for (int i = 0; i < 8; i++)
                #pragma unroll
                for (int j = 0; j < 8; j++)
                    acc[i][j] = fmaf(qr[i], kr[j], acc[i][j]);
        }
        __syncthreads();
    }
    const float scale = 0.125f;
    float* obase = attn + (size_t)bh * Sc * Sc;
    #pragma unroll
    for (int i = 0; i < 8; i++) {
        float* orow = obase + (size_t)(i0 + tr + i) * Sc + j0 + tc;
        #pragma unroll
        for (int j = 0; j < 8; j += 4) {
            float4 o = make_float4(acc[i][j] * scale, acc[i][j + 1] * scale,
                                   acc[i][j + 2] * scale, acc[i][j + 3] * scale);
            *(float4*)(orow + j) = o;
        }
    }
}

// ---------------------------------------------------------------------------
// XL relative bias (contiguous-slab formulation)
// ---------------------------------------------------------------------------
__global__ __launch_bounds__(128) void rpe_bias_kernel(
    const float* __restrict__ qkv, const float* __restrict__ rpe,
    float* __restrict__ attn)
{
    const int h = blockIdx.x / Sc;
    const int i = blockIdx.x % Sc;
    const int r0 = 384 + 24 * (i & 15) - 24 * h - (i >> 4);
    const float* rbase = rpe + (size_t)r0 * 1024;
    __shared__ float Qs[Bc][HDc];
    const int tid = threadIdx.x;
    for (int t = tid; t < Bc * HDc; t += 128) {
        int b = t >> 6, dd = t & 63;
        Qs[b][dd] = qkv[(size_t)(b * Sc + i) * D3c + h * 192 + dd];
    }
    __syncthreads();
    float acc[3][Bc];
    #pragma unroll
    for (int jj = 0; jj < 3; jj++)
        #pragma unroll
        for (int b = 0; b < Bc; b++) acc[jj][b] = 0.f;
    #pragma unroll
    for (int c = 0; c < 16; c++) {
        float4 qv[Bc];
        #pragma unroll
        for (int b = 0; b < Bc; b++) qv[b] = *(const float4*)&Qs[b][c * 4];
        #pragma unroll
        for (int jj = 0; jj < 3; jj++) {
            int j = tid + jj * 128;
            float4 rv = *(const float4*)(rbase + (size_t)j * 64 + c * 4);
            #pragma unroll
            for (int b = 0; b < Bc; b++)
                acc[jj][b] += qv[b].x * rv.x + qv[b].y * rv.y +
                              qv[b].z * rv.z + qv[b].w * rv.w;
        }
    }
    #pragma unroll
    for (int jj = 0; jj < 3; jj++) {
        int j = tid + jj * 128;
        #pragma unroll
        for (int b = 0; b < Bc; b++) {
            size_t idx = ((size_t)(b * Hc + h) * Sc + i) * Sc + j;
            attn[idx] += acc[jj][b];
        }
    }
}

// ---------------------------------------------------------------------------
// In-place row softmax (S=384)
// ---------------------------------------------------------------------------
__global__ __launch_bounds__(128) void softmax_kernel(float* __restrict__ attn)
{
    float* p = attn + (size_t)blockIdx.x * Sc;
    const int tid = threadIdx.x;
    float v[3];
    float m = -1e30f;
    #pragma unroll
    for (int c = 0; c < 3; c++) { v[c] = p[tid + c * 128]; m = fmaxf(m, v[c]); }
    #pragma unroll
    for (int o = 16; o > 0; o >>= 1) m = fmaxf(m, __shfl_xor_sync(0xffffffffu, m, o));
    __shared__ float red[4];
    if ((tid & 31) == 0) red[tid >> 5] = m;
    __syncthreads();
    m = fmaxf(fmaxf(red[0], red[1]), fmaxf(red[2], red[3]));
    __syncthreads();
    float s = 0.f;
    #pragma unroll
    for (int c = 0; c < 3; c++) { v[c] = __expf(v[c] - m); s += v[c]; }
    #pragma unroll
    for (int o = 16; o > 0; o >>= 1) s += __shfl_xor_sync(0xffffffffu, s, o);
    if ((tid & 31) == 0) red[tid >> 5] = s;
    __syncthreads();
    s = red[0] + red[1] + red[2] + red[3];
    const float inv = 1.0f / s;
    #pragma unroll
    for (int c = 0; c < 3; c++) p[tid + c * 128] = v[c] * inv;
}

// ---------------------------------------------------------------------------
// values = attn @ v  (fp32 SIMT)
// ---------------------------------------------------------------------------
__global__ __launch_bounds__(256) void av_kernel(
    const float* __restrict__ attn, const float* __restrict__ qkv,
    float* __restrict__ vals)
{
    const int bh = blockIdx.z;
    const int b = bh >> 4, h = bh & 15;
    const int i0 = blockIdx.y * 128;
    const float* abase = attn + ((size_t)bh * Sc + i0) * Sc;
    const float* vbase = qkv + (size_t)(b * Sc) * D3c + h * 192 + 128;
    __shared__ float As[16][128];
    __shared__ float Vs[16][64];
    const int tid = threadIdx.x;
    const int ar = tid >> 1;
    const int ac = (tid & 1) * 8;
    const int vr = tid >> 4;
    const int vc = (tid & 15) * 4;
    const int tr = (tid >> 4) * 8;
    const int tc = (tid & 15) * 4;
    float acc[8][4] = {};
    for (int j0 = 0; j0 < Sc; j0 += 16) {
        float4 a0 = *(const float4*)&abase[(size_t)ar * Sc + j0 + ac];
        float4 a1 = *(const float4*)&abase[(size_t)ar * Sc + j0 + ac + 4];
        As[ac + 0][ar] = a0.x; As[ac + 1][ar] = a0.y;
        As[ac + 2][ar] = a0.z; As[ac + 3][ar] = a0.w;
        As[ac + 4][ar] = a1.x; As[ac + 5][ar] = a1.y;
        As[ac + 6][ar] = a1.z; As[ac + 7][ar] = a1.w;
        *(float4*)&Vs[vr][vc] = *(const float4*)&vbase[(size_t)(j0 + vr) * D3c + vc];
        __syncthreads();
        #pragma unroll
        for (int kk = 0; kk < 16; kk++) {
            float arg[8], vrg[4];
            #pragma unroll
            for (int u = 0; u < 8; u++) arg[u] = As[kk][tr + u];
            #pragma unroll
            for (int u = 0; u < 4; u++) vrg[u] = Vs[kk][tc + u];
            #pragma unroll
            for (int i = 0; i < 8; i++)
                #pragma unroll
                for (int j = 0; j < 4; j++)
                    acc[i][j] = fmaf(arg[i], vrg[j], acc[i][j]);
        }
        __syncthreads();
    }
    #pragma unroll
    for (int i = 0; i < 8; i++) {
        float4 o = make_float4(acc[i][0], acc[i][1], acc[i][2], acc[i][3]);
        *(float4*)&vals[(size_t)(b * Sc + i0 + tr + i) * Dc + h * 64 + tc] = o;
    }
}

// ---------------------------------------------------------------------------
extern "C" void kernel_launch(void* const* d_in, const int* in_sizes, int n_in,
                              void* d_out, int out_size)
{
    const float* x     = (const float*)d_in[0];
    const float* qkv_w = (const float*)d_in[1];
    const float* qkv_b = (const float*)d_in[2];
    const float* out_w = (const float*)d_in[3];
    const float* out_b = (const float*)d_in[4];
    const float* rpe   = (const float*)d_in[5];

    float *qkvbuf, *valsbuf, *attnscr;
    __nv_bfloat16 *ah, *al, *wqh, *wql, *woh, *wol;
    cudaGetSymbolAddress((void**)&qkvbuf, g_qkv);
    cudaGetSymbolAddress((void**)&valsbuf, g_vals);
    cudaGetSymbolAddress((void**)&attnscr, g_attn);
    cudaGetSymbolAddress((void**)&ah, g_ah);
    cudaGetSymbolAddress((void**)&al, g_al);
    cudaGetSymbolAddress((void**)&wqh, g_wqh);
    cudaGetSymbolAddress((void**)&wql, g_wql);
    cudaGetSymbolAddress((void**)&woh, g_woh);
    cudaGetSymbolAddress((void**)&wol, g_wol);

    float* out = (float*)d_out;
    const long OUT_E = (long)BSc * Dc;
    const long ATT_E = (long)Bc * Hc * Sc * Sc;
    float* attn = ((long)out_size >= OUT_E + ATT_E) ? (out + OUT_E) : attnscr;

    cudaFuncSetAttribute(mma_gemm_kernel,
                         cudaFuncAttributeMaxDynamicSharedMemorySize, GSMEM);

    // prep: bf16 hi/lo splits
    const int n4x = BSc * Dc / 4;
    split_kernel<<<(n4x + 255) / 256, 256>>>(x, ah, al, n4x);
    transpose_split_kernel<<<dim3(D3c / 32, Dc / 32), dim3(32, 8)>>>(qkv_w, wqh, wql, Dc, D3c);
    transpose_split_kernel<<<dim3(Dc / 32, Dc / 32), dim3(32, 8)>>>(out_w, woh, wol, Dc, Dc);

    // 1) qkv = x @ qkv_w + qkv_b   (HMMA tensor cores)
    mma_gemm_kernel<<<dim3(D3c / 128, BSc / 128), 256, GSMEM>>>(
        ah, al, wqh, wql, qkv_b, qkvbuf, BSc, D3c, Dc);
    // 2-5) attention middle (fp32)
    qk_kernel<<<dim3(3, 3, Bc * Hc), 256>>>(qkvbuf, attn);
    rpe_bias_kernel<<<Hc * Sc, 128>>>(qkvbuf, rpe, attn);
    softmax_kernel<<<Bc * Hc * Sc, 128>>>(attn);
    av_kernel<<<dim3(1, 3, Bc * Hc), 256>>>(attn, qkvbuf, valsbuf);
    // 6) out = values @ out_w + out_b   (HMMA tensor cores)
    split_kernel<<<(n4x + 255) / 256, 256>>>(valsbuf, ah, al, n4x);
    mma_gemm_kernel<<<dim3(Dc / 128, BSc / 128), 256, GSMEM>>>(
        ah, al, woh, wol, out_b, out, BSc, Dc, Dc);
}

// round 4
// speedup vs baseline: 1.6678x; 1.1270x over previous
#include <cuda_runtime.h>
#include <cuda_bf16.h>
#include <cstdint>

#define Bc 8
#define Sc 384
#define Dc 1024
#define Hc 16
#define HDc 64
#define D3c 3072
#define BSc 3072   // B*S

// ---------------------------------------------------------------------------
// Scratch (static device globals; no runtime allocation)
// ---------------------------------------------------------------------------
__device__ float g_qkv[(size_t)BSc * D3c];            // qkv projection (fp32)
__device__ float g_attn[(size_t)Bc * Hc * Sc * Sc];   // fallback attn buffer
__device__ __align__(16) __nv_bfloat16 g_ah[(size_t)BSc * Dc];   // A hi (x, then vals)
__device__ __align__(16) __nv_bfloat16 g_al[(size_t)BSc * Dc];   // A lo
__device__ __align__(16) __nv_bfloat16 g_wqh[(size_t)D3c * Dc];  // qkv_w^T hi [N,K]
__device__ __align__(16) __nv_bfloat16 g_wql[(size_t)D3c * Dc];  // qkv_w^T lo
__device__ __align__(16) __nv_bfloat16 g_woh[(size_t)Dc * Dc];   // out_w^T hi
__device__ __align__(16) __nv_bfloat16 g_wol[(size_t)Dc * Dc];   // out_w^T lo

// ---------------------------------------------------------------------------
// Baseline-PTX tensor-core helpers (sm_80+ ISA; valid for compute_103)
// ---------------------------------------------------------------------------
__device__ __forceinline__ uint32_t smem_u32(const void* p) {
    uint32_t a;
    asm("{ .reg .u64 t; cvta.to.shared.u64 t, %1; cvt.u32.u64 %0, t; }" : "=r"(a) : "l"(p));
    return a;
}
#define CP_ASYNC16(sm, gp) \
    asm volatile("cp.async.cg.shared.global [%0], [%1], 16;" :: "r"(sm), "l"(gp))
#define CP_COMMIT() asm volatile("cp.async.commit_group;" ::: "memory")
#define CP_WAIT2()  asm volatile("cp.async.wait_group 2;" ::: "memory")

#define LDSM_X4(r, a) \
    asm volatile("ldmatrix.sync.aligned.m8n8.x4.shared.b16 {%0,%1,%2,%3}, [%4];" \
        : "=r"((r)[0]), "=r"((r)[1]), "=r"((r)[2]), "=r"((r)[3]) : "r"(a))

__device__ __forceinline__ void mma_bf16(float* d, const uint32_t* a,
                                         uint32_t b0, uint32_t b1) {
    asm volatile(
        "mma.sync.aligned.m16n8k16.row.col.f32.bf16.bf16.f32 "
        "{%0,%1,%2,%3}, {%4,%5,%6,%7}, {%8,%9}, {%0,%1,%2,%3};"
        : "+f"(d[0]), "+f"(d[1]), "+f"(d[2]), "+f"(d[3])
        : "r"(a[0]), "r"(a[1]), "r"(a[2]), "r"(a[3]), "r"(b0), "r"(b1));
}

// ---------------------------------------------------------------------------
// HMMA bf16-split GEMM: C = (Ah+Al)[M,K] @ (Bh+Bl)[N,K]^T + bias
//   3-pass: Ah*Bh + Al*Bh + Ah*Bl; pass-sequential fragment loads (low regs).
// CTA 128x128, 8 warps (64x32 warp tile), K-chunk 32, 3-stage cp.async, 2 CTA/SM.
// ---------------------------------------------------------------------------
#define TILE_B 8192                 // one 128x32 bf16 tile
#define BUF_B  (4 * TILE_B)         // Ah,Al,Bh,Bl
#define NSTAGE 3
#define GSMEM  (NSTAGE * BUF_B)     // 96 KB

__global__ __launch_bounds__(256, 2) void mma_gemm_kernel(
    const __nv_bfloat16* __restrict__ Ah, const __nv_bfloat16* __restrict__ Al,
    const __nv_bfloat16* __restrict__ Bh, const __nv_bfloat16* __restrict__ Bl,
    const float* __restrict__ bias, float* __restrict__ C,
    int M, int N, int K)
{
    extern __shared__ char smem[];
    const uint32_t sbase = smem_u32(smem);
    const int tid  = threadIdx.x;
    const int wid  = tid >> 5;
    const int lane = tid & 31;
    const int m0 = blockIdx.y * 128;
    const int n0 = blockIdx.x * 128;
    const int mw = (wid & 1) * 64;     // warp m offset
    const int nw = (wid >> 1) * 32;    // warp n offset

    // cp.async mapping: row = tid>>1, two 16B chunks per thread
    const int lrow = tid >> 1;
    const int c0   = (tid & 1) * 2;
    const int sw0  = (lrow >> 1) & 3;
    const __nv_bfloat16* gAh = Ah + (size_t)(m0 + lrow) * K;
    const __nv_bfloat16* gAl = Al + (size_t)(m0 + lrow) * K;
    const __nv_bfloat16* gBh = Bh + (size_t)(n0 + lrow) * K;
    const __nv_bfloat16* gBl = Bl + (size_t)(n0 + lrow) * K;
    const uint32_t soff0 = lrow * 64 + (((c0 + 0) ^ sw0) << 4);
    const uint32_t soff1 = lrow * 64 + (((c0 + 1) ^ sw0) << 4);

    const int NK = K >> 5;  // 32-wide K chunks

    auto issue = [&](int it) {
        if (it < NK) {
            const uint32_t tb = sbase + (it % NSTAGE) * BUF_B;
            const int k0 = it << 5;
            CP_ASYNC16(tb + 0 * TILE_B + soff0, gAh + k0 + (c0 + 0) * 8);
            CP_ASYNC16(tb + 0 * TILE_B + soff1, gAh + k0 + (c0 + 1) * 8);
            CP_ASYNC16(tb + 1 * TILE_B + soff0, gAl + k0 + (c0 + 0) * 8);
            CP_ASYNC16(tb + 1 * TILE_B + soff1, gAl + k0 + (c0 + 1) * 8);
            CP_ASYNC16(tb + 2 * TILE_B + soff0, gBh + k0 + (c0 + 0) * 8);
            CP_ASYNC16(tb + 2 * TILE_B + soff1, gBh + k0 + (c0 + 1) * 8);
            CP_ASYNC16(tb + 3 * TILE_B + soff0, gBl + k0 + (c0 + 0) * 8);
            CP_ASYNC16(tb + 3 * TILE_B + soff1, gBl + k0 + (c0 + 1) * 8);
        }
        CP_COMMIT();
    };

    // ldmatrix addressing: row = rbase + (lane&15), 16B col = lane>>4
    const int frow = lane & 15;
    const int fc   = lane >> 4;
    auto fr_addr = [&](int rbase) -> uint32_t {
        const int row = rbase + frow;
        return (uint32_t)(row * 64 + ((fc ^ ((row >> 1) & 3)) << 4));
    };
    const uint32_t aoff = fr_addr(mw);
    const uint32_t boff = fr_addr(nw);

    float acc[4][4][4];
    #pragma unroll
    for (int i = 0; i < 4; i++)
        #pragma unroll
        for (int j = 0; j < 4; j++)
            #pragma unroll
            for (int r = 0; r < 4; r++) acc[i][j][r] = 0.f;

    issue(0); issue(1); issue(2);

    for (int it = 0; it < NK; it++) {
        CP_WAIT2();
        __syncthreads();
        const uint32_t tb = sbase + (it % NSTAGE) * BUF_B;
        #pragma unroll
        for (int ks = 0; ks < 2; ks++) {
            const uint32_t kx = ks ? 32u : 0u;
            // pass 0: Ah*Bh   pass 1: Al*Bh   pass 2: Ah*Bl
            #pragma unroll
            for (int p = 0; p < 3; p++) {
                const uint32_t at = tb + (p == 1 ? TILE_B : 0);
                const uint32_t bt = tb + (p == 2 ? 3 * TILE_B : 2 * TILE_B);
                uint32_t af[4][4], bf[2][4];
                #pragma unroll
                for (int mt = 0; mt < 4; mt++)
                    LDSM_X4(af[mt], at + ((aoff + mt * 1024) ^ kx));
                #pragma unroll
                for (int btt = 0; btt < 2; btt++)
                    LDSM_X4(bf[btt], bt + ((boff + btt * 1024) ^ kx));
                #pragma unroll
                for (int mt = 0; mt < 4; mt++)
                    #pragma unroll
                    for (int nt = 0; nt < 4; nt++)
                        mma_bf16(acc[mt][nt], af[mt],
                                 bf[nt >> 1][nt & 1], bf[nt >> 1][(nt & 1) + 2]);
            }
        }
        __syncthreads();
        issue(it + NSTAGE);
    }

    // epilogue
    const int er = lane >> 2;
    const int ec = (lane & 3) * 2;
    #pragma unroll
    for (int mt = 0; mt < 4; mt++) {
        #pragma unroll
        for (int nt = 0; nt < 4; nt++) {
            const int col = n0 + nw + nt * 8 + ec;
            const float bx = __ldg(&bias[col]);
            const float by = __ldg(&bias[col + 1]);
            const int r0 = m0 + mw + mt * 16 + er;
            float2 v0 = make_float2(acc[mt][nt][0] + bx, acc[mt][nt][1] + by);
            float2 v1 = make_float2(acc[mt][nt][2] + bx, acc[mt][nt][3] + by);
            *(float2*)(C + (size_t)r0 * N + col) = v0;
            *(float2*)(C + (size_t)(r0 + 8) * N + col) = v1;
        }
    }
}

// ---------------------------------------------------------------------------
// fp32 -> bf16 hi/lo split (vectorized by 4)
// ---------------------------------------------------------------------------
__global__ __launch_bounds__(256) void split_kernel(
    const float* __restrict__ src, __nv_bfloat16* __restrict__ hi,
    __nv_bfloat16* __restrict__ lo, int n4)
{
    int i = blockIdx.x * blockDim.x + threadIdx.x;
    if (i >= n4) return;
    float4 v = ((const float4*)src)[i];
    __nv_bfloat16 h0 = __float2bfloat16(v.x), h1 = __float2bfloat16(v.y);
    __nv_bfloat16 h2 = __float2bfloat16(v.z), h3 = __float2bfloat16(v.w);
    __nv_bfloat16 l0 = __float2bfloat16(v.x - __bfloat162float(h0));
    __nv_bfloat16 l1 = __float2bfloat16(v.y - __bfloat162float(h1));
    __nv_bfloat16 l2 = __float2bfloat16(v.z - __bfloat162float(h2));
    __nv_bfloat16 l3 = __float2bfloat16(v.w - __bfloat162float(h3));
    ((__nv_bfloat162*)hi)[2 * i]     = __nv_bfloat162(h0, h1);
    ((__nv_bfloat162*)hi)[2 * i + 1] = __nv_bfloat162(h2, h3);
    ((__nv_bfloat162*)lo)[2 * i]     = __nv_bfloat162(l0, l1);
    ((__nv_bfloat162*)lo)[2 * i + 1] = __nv_bfloat162(l2, l3);
}

// ---------------------------------------------------------------------------
// W[K,N] -> Wt[N,K] with bf16 hi/lo split
// ---------------------------------------------------------------------------
__global__ __launch_bounds__(256) void transpose_split_kernel(
    const float* __restrict__ W, __nv_bfloat16* __restrict__ Th,
    __nv_bfloat16* __restrict__ Tl, int K, int N)
{
    __shared__ float t[32][33];
    const int n0 = blockIdx.x * 32, k0 = blockIdx.y * 32;
    const int tx = threadIdx.x, ty = threadIdx.y;
    #pragma unroll
    for (int r = 0; r < 4; r++)
        t[ty + 8 * r][tx] = W[(size_t)(k0 + ty + 8 * r) * N + n0 + tx];
    __syncthreads();
    #pragma unroll
    for (int r = 0; r < 4; r++) {
        float v = t[tx][ty + 8 * r];
        __nv_bfloat16 h = __float2bfloat16(v);
        __nv_bfloat16 l = __float2bfloat16(v - __bfloat162float(h));
        size_t o = (size_t)(n0 + ty + 8 * r) * K + k0 + tx;
        Th[o] = h; Tl[o] = l;
    }
}

// ---------------------------------------------------------------------------
// logits[b,h,i,j] = scale * q . k   (fp32 SIMT)
// ---------------------------------------------------------------------------
__global__ __launch_bounds__(256) void qk_kernel(
    const float* __restrict__ qkv, float* __restrict__ attn)
{
    const int bh = blockIdx.z;
    const int b = bh >> 4, h = bh & 15;
    const float* qbase = qkv + (size_t)(b * Sc) * D3c + h * 192;
    const float* kbase = qbase + 64;
    const int i0 = blockIdx.y * 128, j0 = blockIdx.x * 128;
    __shared__ float Qs[8][128], Ks[8][128];
    const int tid = threadIdx.x;
    const int lr = tid >> 1;
    const int lc = (tid & 1) * 4;
    const int tr = (tid >> 4) * 8;
    const int tc = (tid & 15) * 8;
    float acc[8][8] = {};
    for (int k0 = 0; k0 < HDc; k0 += 8) {
        float4 qv = *(const float4*)&qbase[(size_t)(i0 + lr) * D3c + k0 + lc];
        Qs[lc + 0][lr] = qv.x; Qs[lc + 1][lr] = qv.y;
        Qs[lc + 2][lr] = qv.z; Qs[lc + 3][lr] = qv.w;
        float4 kv = *(const float4*)&kbase[(size_t)(j0 + lr) * D3c + k0 + lc];
        Ks[lc + 0][lr] = kv.x; Ks[lc + 1][lr] = kv.y;
        Ks[lc + 2][lr] = kv.z; Ks[lc + 3][lr] = kv.w;
        __syncthreads();
        #pragma unroll
        for (int kk = 0; kk < 8; kk++) {
            float qr[8], kr[8];
            #pragma unroll
            for (int u = 0; u < 8; u++) qr[u] = Qs[kk][tr + u];
            #pragma unroll
            for (int u = 0; u < 8; u++) kr[u] = Ks[kk][tc + u];
            #pragma unroll
            for (int i = 0; i < 8; i++)
                #pragma unroll
                for (int j = 0; j < 8; j++)
                    acc[i][j] = fmaf(qr[i], kr[j], acc[i][j]);
        }
        __syncthreads();
    }
    const float scale = 0.125f;
    float* obase = attn + (size_t)bh * Sc * Sc;
    #pragma unroll
    for (int i = 0; i < 8; i++) {
        float* orow = obase + (size_t)(i0 + tr + i) * Sc + j0 + tc;
        #pragma unroll
        for (int j = 0; j < 8; j += 4) {
            float4 o = make_float4(acc[i][j] * scale, acc[i][j + 1] * scale,
                                   acc[i][j + 2] * scale, acc[i][j + 3] * scale);
            *(float4*)(orow + j) = o;
        }
    }
}

// ---------------------------------------------------------------------------
// Fused XL relative bias + row softmax.
// Block = (h,i). rpem slab is contiguous: r0 = 384 + 24*(i&15) - 24*h - (i>>4).
// Computes bias[j] = q[b,h,i,:] . rpe[r0*1024 + 64*j : +64] for all 8 b,
// adds to logits, then softmaxes each (b) row in smem and writes attn.
// ---------------------------------------------------------------------------
__global__ __launch_bounds__(128) void rpe_softmax_kernel(
    const float* __restrict__ qkv, const float* __restrict__ rpe,
    float* __restrict__ attn)
{
    const int h = blockIdx.x / Sc;
    const int i = blockIdx.x % Sc;
    const int r0 = 384 + 24 * (i & 15) - 24 * h - (i >> 4);
    const float* rbase = rpe + (size_t)r0 * 1024;
    __shared__ float Qs[Bc][HDc];
    __shared__ float L[Bc][Sc];
    const int tid = threadIdx.x;
    for (int t = tid; t < Bc * HDc; t += 128) {
        int b = t >> 6, dd = t & 63;
        Qs[b][dd] = qkv[(size_t)(b * Sc + i) * D3c + h * 192 + dd];
    }
    __syncthreads();

    float acc[3][Bc];
    #pragma unroll
    for (int jj = 0; jj < 3; jj++)
        #pragma unroll
        for (int b = 0; b < Bc; b++) acc[jj][b] = 0.f;
    #pragma unroll
    for (int c = 0; c < 16; c++) {
        float4 qv[Bc];
        #pragma unroll
        for (int b = 0; b < Bc; b++) qv[b] = *(const float4*)&Qs[b][c * 4];
        #pragma unroll
        for (int jj = 0; jj < 3; jj++) {
            int j = tid + jj * 128;
            float4 rv = *(const float4*)(rbase + (size_t)j * 64 + c * 4);
            #pragma unroll
            for (int b = 0; b < Bc; b++)
                acc[jj][b] += qv[b].x * rv.x + qv[b].y * rv.y +
                              qv[b].z * rv.z + qv[b].w * rv.w;
        }
    }
    // logits = qk (already scaled) + bias -> smem
    #pragma unroll
    for (int jj = 0; jj < 3; jj++) {
        const int j = tid + jj * 128;
        #pragma unroll
        for (int b = 0; b < Bc; b++) {
            size_t idx = ((size_t)(b * Hc + h) * Sc + i) * Sc + j;
            L[b][j] = attn[idx] + acc[jj][b];
        }
    }
    __syncthreads();

    // softmax: warp w handles rows b = 2w, 2w+1 (12 elems/lane each)
    const int wrp = tid >> 5, lane = tid & 31;
    #pragma unroll
    for (int bb = 0; bb < 2; bb++) {
        const int b = wrp * 2 + bb;
        float v[12];
        float m = -1e30f;
        #pragma unroll
        for (int r = 0; r < 12; r++) { v[r] = L[b][lane + 32 * r]; m = fmaxf(m, v[r]); }
        #pragma unroll
        for (int o = 16; o > 0; o >>= 1) m = fmaxf(m, __shfl_xor_sync(0xffffffffu, m, o));
        float s = 0.f;
        #pragma unroll
        for (int r = 0; r < 12; r++) { v[r] = __expf(v[r] - m); s += v[r]; }
        #pragma unroll
        for (int o = 16; o > 0; o >>= 1) s += __shfl_xor_sync(0xffffffffu, s, o);
        const float inv = 1.0f / s;
        float* orow = attn + ((size_t)(b * Hc + h) * Sc + i) * Sc;
        #pragma unroll
        for (int r = 0; r < 12; r++) orow[lane + 32 * r] = v[r] * inv;
    }
}

// ---------------------------------------------------------------------------
// values = attn @ v, written directly as bf16 hi/lo in (b,s,d) layout
// ---------------------------------------------------------------------------
__global__ __launch_bounds__(256) void av_kernel(
    const float* __restrict__ attn, const float* __restrict__ qkv,
    __nv_bfloat16* __restrict__ vh, __nv_bfloat16* __restrict__ vl)
{
    const int bh = blockIdx.z;
    const int b = bh >> 4, h = bh & 15;
    const int i0 = blockIdx.y * 128;
    const float* abase = attn + ((size_t)bh * Sc + i0) * Sc;
    const float* vbase = qkv + (size_t)(b * Sc) * D3c + h * 192 + 128;
    __shared__ float As[16][128];
    __shared__ float Vs[16][64];
    const int tid = threadIdx.x;
    const int ar = tid >> 1;
    const int ac = (tid & 1) * 8;
    const int vr = tid >> 4;
    const int vc = (tid & 15) * 4;
    const int tr = (tid >> 4) * 8;
    const int tc = (tid & 15) * 4;
    float acc[8][4] = {};
    for (int j0 = 0; j0 < Sc; j0 += 16) {
        float4 a0 = *(const float4*)&abase[(size_t)ar * Sc + j0 + ac];
        float4 a1 = *(const float4*)&abase[(size_t)ar * Sc + j0 + ac + 4];
        As[ac + 0][ar] = a0.x; As[ac + 1][ar] = a0.y;
        As[ac + 2][ar] = a0.z; As[ac + 3][ar] = a0.w;
        As[ac + 4][ar] = a1.x; As[ac + 5][ar] = a1.y;
        As[ac + 6][ar] = a1.z; As[ac + 7][ar] = a1.w;
        *(float4*)&Vs[vr][vc] = *(const float4*)&vbase[(size_t)(j0 + vr) * D3c + vc];
        __syncthreads();
        #pragma unroll
        for (int kk = 0; kk < 16; kk++) {
            float arg[8], vrg[4];
            #pragma unroll
            for (int u = 0; u < 8; u++) arg[u] = As[kk][tr + u];
            #pragma unroll
            for (int u = 0; u < 4; u++) vrg[u] = Vs[kk][tc + u];
            #pragma unroll
            for (int i = 0; i < 8; i++)
                #pragma unroll
                for (int j = 0; j < 4; j++)
                    acc[i][j] = fmaf(arg[i], vrg[j], acc[i][j]);
        }
        __syncthreads();
    }
    #pragma unroll
    for (int i = 0; i < 8; i++) {
        const size_t o = (size_t)(b * Sc + i0 + tr + i) * Dc + h * 64 + tc;
        __nv_bfloat16 h0 = __float2bfloat16(acc[i][0]);
        __nv_bfloat16 h1 = __float2bfloat16(acc[i][1]);
        __nv_bfloat16 h2 = __float2bfloat16(acc[i][2]);
        __nv_bfloat16 h3 = __float2bfloat16(acc[i][3]);
        __nv_bfloat16 l0 = __float2bfloat16(acc[i][0] - __bfloat162float(h0));
        __nv_bfloat16 l1 = __float2bfloat16(acc[i][1] - __bfloat162float(h1));
        __nv_bfloat16 l2 = __float2bfloat16(acc[i][2] - __bfloat162float(h2));
        __nv_bfloat16 l3 = __float2bfloat16(acc[i][3] - __bfloat162float(h3));
        *(__nv_bfloat162*)(vh + o)     = __nv_bfloat162(h0, h1);
        *(__nv_bfloat162*)(vh + o + 2) = __nv_bfloat162(h2, h3);
        *(__nv_bfloat162*)(vl + o)     = __nv_bfloat162(l0, l1);
        *(__nv_bfloat162*)(vl + o + 2) = __nv_bfloat162(l2, l3);
    }
}

// ---------------------------------------------------------------------------
extern "C" void kernel_launch(void* const* d_in, const int* in_sizes, int n_in,
                              void* d_out, int out_size)
{
    const float* x     = (const float*)d_in[0];
    const float* qkv_w = (const float*)d_in[1];
    const float* qkv_b = (const float*)d_in[2];
    const float* out_w = (const float*)d_in[3];
    const float* out_b = (const float*)d_in[4];
    const float* rpe   = (const float*)d_in[5];

    float *qkvbuf, *attnscr;
    __nv_bfloat16 *ah, *al, *wqh, *wql, *woh, *wol;
    cudaGetSymbolAddress((void**)&qkvbuf, g_qkv);
    cudaGetSymbolAddress((void**)&attnscr, g_attn);
    cudaGetSymbolAddress((void**)&ah, g_ah);
    cudaGetSymbolAddress((void**)&al, g_al);
    cudaGetSymbolAddress((void**)&wqh, g_wqh);
    cudaGetSymbolAddress((void**)&wql, g_wql);
    cudaGetSymbolAddress((void**)&woh, g_woh);
    cudaGetSymbolAddress((void**)&wol, g_wol);

    float* out = (float*)d_out;
    const long OUT_E = (long)BSc * Dc;
    const long ATT_E = (long)Bc * Hc * Sc * Sc;
    float* attn = ((long)out_size >= OUT_E + ATT_E) ? (out + OUT_E) : attnscr;

    cudaFuncSetAttribute(mma_gemm_kernel,
                         cudaFuncAttributeMaxDynamicSharedMemorySize, GSMEM);

    // prep: bf16 hi/lo splits
    const int n4x = BSc * Dc / 4;
    split_kernel<<<(n4x + 255) / 256, 256>>>(x, ah, al, n4x);
    transpose_split_kernel<<<dim3(D3c / 32, Dc / 32), dim3(32, 8)>>>(qkv_w, wqh, wql, Dc, D3c);
    transpose_split_kernel<<<dim3(Dc / 32, Dc / 32), dim3(32, 8)>>>(out_w, woh, wol, Dc, Dc);

    // 1) qkv = x @ qkv_w + qkv_b   (HMMA)
    mma_gemm_kernel<<<dim3(D3c / 128, BSc / 128), 256, GSMEM>>>(
        ah, al, wqh, wql, qkv_b, qkvbuf, BSc, D3c, Dc);
    // 2) logits = scale * q k^T
    qk_kernel<<<dim3(3, 3, Bc * Hc), 256>>>(qkvbuf, attn);
    // 3+4) += rpe bias, softmax (fused)
    rpe_softmax_kernel<<<Hc * Sc, 128>>>(qkvbuf, rpe, attn);
    // 5) values = attn @ v -> bf16 hi/lo directly
    av_kernel<<<dim3(1, 3, Bc * Hc), 256>>>(attn, qkvbuf, ah, al);
    // 6) out = values @ out_w + out_b   (HMMA)
    mma_gemm_kernel<<<dim3(Dc / 128, BSc / 128), 256, GSMEM>>>(
        ah, al, woh, wol, out_b, out, BSc, Dc, Dc);
}

// round 5
// speedup vs baseline: 1.8491x; 1.1087x over previous
#include <cuda_runtime.h>
#include <cuda_bf16.h>
#include <cstdint>

#define Bc 8
#define Sc 384
#define Dc 1024
#define Hc 16
#define HDc 64
#define D3c 3072
#define BSc 3072   // B*S

// ---------------------------------------------------------------------------
// Scratch (static device globals; no runtime allocation)
// ---------------------------------------------------------------------------
__device__ float g_qkv[(size_t)BSc * D3c];            // qkv projection (fp32)
__device__ float g_attn[(size_t)Bc * Hc * Sc * Sc];   // fallback attn buffer
__device__ __align__(16) __nv_bfloat16 g_ah[(size_t)BSc * Dc];    // A hi (x, then vals)
__device__ __align__(16) __nv_bfloat16 g_al[(size_t)BSc * Dc];    // A lo
__device__ __align__(16) __nv_bfloat16 g_wqh[(size_t)D3c * Dc];   // qkv_w^T hi [N,K]
__device__ __align__(16) __nv_bfloat16 g_wql[(size_t)D3c * Dc];   // qkv_w^T lo
__device__ __align__(16) __nv_bfloat16 g_woh[(size_t)Dc * Dc];    // out_w^T hi
__device__ __align__(16) __nv_bfloat16 g_wol[(size_t)Dc * Dc];    // out_w^T lo
__device__ __align__(16) __nv_bfloat16 g_qkvh[(size_t)BSc * D3c]; // qkv hi (q pre-scaled)
__device__ __align__(16) __nv_bfloat16 g_qkvl[(size_t)BSc * D3c]; // qkv lo
__device__ __align__(16) __nv_bfloat16 g_ath[(size_t)Bc * Hc * Sc * Sc]; // attn hi
__device__ __align__(16) __nv_bfloat16 g_atl[(size_t)Bc * Hc * Sc * Sc]; // attn lo

// ---------------------------------------------------------------------------
// Baseline-PTX tensor-core helpers
// ---------------------------------------------------------------------------
__device__ __forceinline__ uint32_t smem_u32(const void* p) {
    uint32_t a;
    asm("{ .reg .u64 t; cvta.to.shared.u64 t, %1; cvt.u32.u64 %0, t; }" : "=r"(a) : "l"(p));
    return a;
}
#define CP_ASYNC16(sm, gp) \
    asm volatile("cp.async.cg.shared.global [%0], [%1], 16;" :: "r"(sm), "l"(gp))
#define CP_COMMIT() asm volatile("cp.async.commit_group;" ::: "memory")
#define CP_WAIT0()  asm volatile("cp.async.wait_group 0;" ::: "memory")
#define CP_WAIT1()  asm volatile("cp.async.wait_group 1;" ::: "memory")
#define CP_WAIT2()  asm volatile("cp.async.wait_group 2;" ::: "memory")

#define LDSM_X4(r, a) \
    asm volatile("ldmatrix.sync.aligned.m8n8.x4.shared.b16 {%0,%1,%2,%3}, [%4];" \
        : "=r"((r)[0]), "=r"((r)[1]), "=r"((r)[2]), "=r"((r)[3]) : "r"(a))
#define LDSM_X4_T(r, a) \
    asm volatile("ldmatrix.sync.aligned.m8n8.x4.trans.shared.b16 {%0,%1,%2,%3}, [%4];" \
        : "=r"((r)[0]), "=r"((r)[1]), "=r"((r)[2]), "=r"((r)[3]) : "r"(a))

__device__ __forceinline__ void mma_bf16(float* d, const uint32_t* a,
                                         uint32_t b0, uint32_t b1) {
    asm volatile(
        "mma.sync.aligned.m16n8k16.row.col.f32.bf16.bf16.f32 "
        "{%0,%1,%2,%3}, {%4,%5,%6,%7}, {%8,%9}, {%0,%1,%2,%3};"
        : "+f"(d[0]), "+f"(d[1]), "+f"(d[2]), "+f"(d[3])
        : "r"(a[0]), "r"(a[1]), "r"(a[2]), "r"(a[3]), "r"(b0), "r"(b1));
}

__device__ __forceinline__ void split2(float x, float y,
                                       __nv_bfloat16* ph, __nv_bfloat16* pl) {
    __nv_bfloat16 hx = __float2bfloat16(x), hy = __float2bfloat16(y);
    *(__nv_bfloat162*)ph = __nv_bfloat162(hx, hy);
    *(__nv_bfloat162*)pl = __nv_bfloat162(
        __float2bfloat16(x - __bfloat162float(hx)),
        __float2bfloat16(y - __bfloat162float(hy)));
}

// ---------------------------------------------------------------------------
// HMMA bf16-split GEMM: C = (Ah+Al)@(Bh+Bl)^T + bias; optional bf16 hi/lo
// emission of C (qkv_mode: scale q columns by 0.125 in the bf16 copies).
// ---------------------------------------------------------------------------
#define TILE_B 8192
#define BUF_B  (4 * TILE_B)
#define NSTAGE 3
#define GSMEM  (NSTAGE * BUF_B)   // 96 KB

__global__ __launch_bounds__(256, 2) void mma_gemm_kernel(
    const __nv_bfloat16* __restrict__ Ah, const __nv_bfloat16* __restrict__ Al,
    const __nv_bfloat16* __restrict__ Bh, const __nv_bfloat16* __restrict__ Bl,
    const float* __restrict__ bias, float* __restrict__ C,
    __nv_bfloat16* __restrict__ Ch, __nv_bfloat16* __restrict__ Cl,
    int qkv_mode, int M, int N, int K)
{
    extern __shared__ char smem[];
    const uint32_t sbase = smem_u32(smem);
    const int tid  = threadIdx.x;
    const int wid  = tid >> 5;
    const int lane = tid & 31;
    const int m0 = blockIdx.y * 128;
    const int n0 = blockIdx.x * 128;
    const int mw = (wid & 1) * 64;
    const int nw = (wid >> 1) * 32;

    const int lrow = tid >> 1;
    const int c0   = (tid & 1) * 2;
    const int sw0  = (lrow >> 1) & 3;
    const __nv_bfloat16* gAh = Ah + (size_t)(m0 + lrow) * K;
    const __nv_bfloat16* gAl = Al + (size_t)(m0 + lrow) * K;
    const __nv_bfloat16* gBh = Bh + (size_t)(n0 + lrow) * K;
    const __nv_bfloat16* gBl = Bl + (size_t)(n0 + lrow) * K;
    const uint32_t soff0 = lrow * 64 + (((c0 + 0) ^ sw0) << 4);
    const uint32_t soff1 = lrow * 64 + (((c0 + 1) ^ sw0) << 4);

    const int NK = K >> 5;

    auto issue = [&](int it) {
        if (it < NK) {
            const uint32_t tb = sbase + (it % NSTAGE) * BUF_B;
            const int k0 = it << 5;
            CP_ASYNC16(tb + 0 * TILE_B + soff0, gAh + k0 + (c0 + 0) * 8);
            CP_ASYNC16(tb + 0 * TILE_B + soff1, gAh + k0 + (c0 + 1) * 8);
            CP_ASYNC16(tb + 1 * TILE_B + soff0, gAl + k0 + (c0 + 0) * 8);
            CP_ASYNC16(tb + 1 * TILE_B + soff1, gAl + k0 + (c0 + 1) * 8);
            CP_ASYNC16(tb + 2 * TILE_B + soff0, gBh + k0 + (c0 + 0) * 8);
            CP_ASYNC16(tb + 2 * TILE_B + soff1, gBh + k0 + (c0 + 1) * 8);
            CP_ASYNC16(tb + 3 * TILE_B + soff0, gBl + k0 + (c0 + 0) * 8);
            CP_ASYNC16(tb + 3 * TILE_B + soff1, gBl + k0 + (c0 + 1) * 8);
        }
        CP_COMMIT();
    };

    const int frow = lane & 15;
    const int fc   = lane >> 4;
    auto fr_addr = [&](int rbase) -> uint32_t {
        const int row = rbase + frow;
        return (uint32_t)(row * 64 + ((fc ^ ((row >> 1) & 3)) << 4));
    };
    const uint32_t aoff = fr_addr(mw);
    const uint32_t boff = fr_addr(nw);

    float acc[4][4][4];
    #pragma unroll
    for (int i = 0; i < 4; i++)
        #pragma unroll
        for (int j = 0; j < 4; j++)
            #pragma unroll
            for (int r = 0; r < 4; r++) acc[i][j][r] = 0.f;

    issue(0); issue(1); issue(2);

    for (int it = 0; it < NK; it++) {
        CP_WAIT2();
        __syncthreads();
        const uint32_t tb = sbase + (it % NSTAGE) * BUF_B;
        #pragma unroll
        for (int ks = 0; ks < 2; ks++) {
            const uint32_t kx = ks ? 32u : 0u;
            #pragma unroll
            for (int p = 0; p < 3; p++) {
                const uint32_t at = tb + (p == 1 ? TILE_B : 0);
                const uint32_t bt = tb + (p == 2 ? 3 * TILE_B : 2 * TILE_B);
                uint32_t af[4][4], bf[2][4];
                #pragma unroll
                for (int mt = 0; mt < 4; mt++)
                    LDSM_X4(af[mt], at + ((aoff + mt * 1024) ^ kx));
                #pragma unroll
                for (int btt = 0; btt < 2; btt++)
                    LDSM_X4(bf[btt], bt + ((boff + btt * 1024) ^ kx));
                #pragma unroll
                for (int mt = 0; mt < 4; mt++)
                    #pragma unroll
                    for (int nt = 0; nt < 4; nt++)
                        mma_bf16(acc[mt][nt], af[mt],
                                 bf[nt >> 1][nt & 1], bf[nt >> 1][(nt & 1) + 2]);
            }
        }
        __syncthreads();
        issue(it + NSTAGE);
    }

    const int er = lane >> 2;
    const int ec = (lane & 3) * 2;
    #pragma unroll
    for (int mt = 0; mt < 4; mt++) {
        #pragma unroll
        for (int nt = 0; nt < 4; nt++) {
            const int col = n0 + nw + nt * 8 + ec;
            const float bx = __ldg(&bias[col]);
            const float by = __ldg(&bias[col + 1]);
            const int r0 = m0 + mw + mt * 16 + er;
            float2 v0 = make_float2(acc[mt][nt][0] + bx, acc[mt][nt][1] + by);
            float2 v1 = make_float2(acc[mt][nt][2] + bx, acc[mt][nt][3] + by);
            *(float2*)(C + (size_t)r0 * N + col) = v0;
            *(float2*)(C + (size_t)(r0 + 8) * N + col) = v1;
            if (Ch) {
                const float s = (qkv_mode && (((col >> 6) % 3) == 0)) ? 0.125f : 1.0f;
                split2(v0.x * s, v0.y * s, Ch + (size_t)r0 * N + col,
                       Cl + (size_t)r0 * N + col);
                split2(v1.x * s, v1.y * s, Ch + (size_t)(r0 + 8) * N + col,
                       Cl + (size_t)(r0 + 8) * N + col);
            }
        }
    }
}

// ---------------------------------------------------------------------------
// fp32 -> bf16 hi/lo split (vectorized by 4)
// ---------------------------------------------------------------------------
__global__ __launch_bounds__(256) void split_kernel(
    const float* __restrict__ src, __nv_bfloat16* __restrict__ hi,
    __nv_bfloat16* __restrict__ lo, int n4)
{
    int i = blockIdx.x * blockDim.x + threadIdx.x;
    if (i >= n4) return;
    float4 v = ((const float4*)src)[i];
    split2(v.x, v.y, hi + 4 * (size_t)i, lo + 4 * (size_t)i);
    split2(v.z, v.w, hi + 4 * (size_t)i + 2, lo + 4 * (size_t)i + 2);
}

// ---------------------------------------------------------------------------
// W[K,N] -> Wt[N,K] with bf16 hi/lo split
// ---------------------------------------------------------------------------
__global__ __launch_bounds__(256) void transpose_split_kernel(
    const float* __restrict__ W, __nv_bfloat16* __restrict__ Th,
    __nv_bfloat16* __restrict__ Tl, int K, int N)
{
    __shared__ float t[32][33];
    const int n0 = blockIdx.x * 32, k0 = blockIdx.y * 32;
    const int tx = threadIdx.x, ty = threadIdx.y;
    #pragma unroll
    for (int r = 0; r < 4; r++)
        t[ty + 8 * r][tx] = W[(size_t)(k0 + ty + 8 * r) * N + n0 + tx];
    __syncthreads();
    #pragma unroll
    for (int r = 0; r < 4; r++) {
        float v = t[tx][ty + 8 * r];
        __nv_bfloat16 h = __float2bfloat16(v);
        __nv_bfloat16 l = __float2bfloat16(v - __bfloat162float(h));
        size_t o = (size_t)(n0 + ty + 8 * r) * K + k0 + tx;
        Th[o] = h; Tl[o] = l;
    }
}

// ---------------------------------------------------------------------------
// qk HMMA: logits[b,h,i,j] = (scaled q) . k, 3-pass bf16 split.
// grid (3,3,B*H); CTA tile 128x128, K=64. SMEM: qh,ql,kh,kl 16KB each.
// Rows are 64 bf16 = 128B; swizzle chunk c -> c ^ (row&7).
// ---------------------------------------------------------------------------
#define QK_SMEM (4 * 16384)

__global__ __launch_bounds__(256, 2) void qk_mma_kernel(
    const __nv_bfloat16* __restrict__ qkvh, const __nv_bfloat16* __restrict__ qkvl,
    float* __restrict__ attn)
{
    extern __shared__ char smem[];
    const uint32_t sb = smem_u32(smem);
    const int tid = threadIdx.x, wid = tid >> 5, lane = tid & 31;
    const int bh = blockIdx.z, b = bh >> 4, h = bh & 15;
    const int i0 = blockIdx.y * 128, j0 = blockIdx.x * 128;

    // tiles: 0=qh 1=ql 2=kh 3=kl
    #pragma unroll
    for (int t = 0; t < 4; t++) {
        const __nv_bfloat16* base = (t & 1) ? qkvl : qkvh;
        const int roff = (t < 2) ? i0 : j0;
        const int coff = h * 192 + ((t < 2) ? 0 : 64);
        for (int idx = tid; idx < 1024; idx += 256) {
            const int row = idx >> 3, c = idx & 7;
            const uint32_t dst = sb + t * 16384 + row * 128 + ((c ^ (row & 7)) << 4);
            CP_ASYNC16(dst, base + (size_t)(b * Sc + roff + row) * D3c + coff + c * 8);
        }
    }
    CP_COMMIT(); CP_WAIT0();
    __syncthreads();

    const int mw = (wid & 1) * 64;
    const int nw = (wid >> 1) * 32;
    const int frow = lane & 15, fc = lane >> 4;

    float acc[4][4][4];
    #pragma unroll
    for (int i = 0; i < 4; i++)
        #pragma unroll
        for (int j = 0; j < 4; j++)
            #pragma unroll
            for (int r = 0; r < 4; r++) acc[i][j][r] = 0.f;

    #pragma unroll
    for (int ks = 0; ks < 4; ks++) {
        uint32_t aadr[4], badr[2];
        #pragma unroll
        for (int mt = 0; mt < 4; mt++) {
            const int row = mw + mt * 16 + frow;
            aadr[mt] = row * 128 + (((2 * ks + fc) ^ (row & 7)) << 4);
        }
        #pragma unroll
        for (int bt = 0; bt < 2; bt++) {
            const int row = nw + bt * 16 + frow;
            badr[bt] = row * 128 + (((2 * ks + fc) ^ (row & 7)) << 4);
        }
        #pragma unroll
        for (int p = 0; p < 3; p++) {
            const uint32_t at = sb + (p == 1 ? 16384 : 0);
            const uint32_t bt_ = sb + (p == 2 ? 3 * 16384 : 2 * 16384);
            uint32_t af[4][4], bf[2][4];
            #pragma unroll
            for (int mt = 0; mt < 4; mt++) LDSM_X4(af[mt], at + aadr[mt]);
            #pragma unroll
            for (int bt = 0; bt < 2; bt++) LDSM_X4(bf[bt], bt_ + badr[bt]);
            #pragma unroll
            for (int mt = 0; mt < 4; mt++)
                #pragma unroll
                for (int nt = 0; nt < 4; nt++)
                    mma_bf16(acc[mt][nt], af[mt],
                             bf[nt >> 1][nt & 1], bf[nt >> 1][(nt & 1) + 2]);
        }
    }

    const int er = lane >> 2, ec = (lane & 3) * 2;
    float* ob = attn + (size_t)bh * Sc * Sc;
    #pragma unroll
    for (int mt = 0; mt < 4; mt++) {
        #pragma unroll
        for (int nt = 0; nt < 4; nt++) {
            const int r0 = i0 + mw + mt * 16 + er;
            const int col = j0 + nw + nt * 8 + ec;
            *(float2*)(ob + (size_t)r0 * Sc + col) =
                make_float2(acc[mt][nt][0], acc[mt][nt][1]);
            *(float2*)(ob + (size_t)(r0 + 8) * Sc + col) =
                make_float2(acc[mt][nt][2], acc[mt][nt][3]);
        }
    }
}

// ---------------------------------------------------------------------------
// Fused XL relative bias + row softmax; also emits attn as bf16 hi/lo.
// ---------------------------------------------------------------------------
__global__ __launch_bounds__(128) void rpe_softmax_kernel(
    const float* __restrict__ qkv, const float* __restrict__ rpe,
    float* __restrict__ attn, __nv_bfloat16* __restrict__ ath,
    __nv_bfloat16* __restrict__ atl)
{
    const int h = blockIdx.x / Sc;
    const int i = blockIdx.x % Sc;
    const int r0 = 384 + 24 * (i & 15) - 24 * h - (i >> 4);
    const float* rbase = rpe + (size_t)r0 * 1024;
    __shared__ float Qs[Bc][HDc];
    __shared__ float L[Bc][Sc];
    const int tid = threadIdx.x;
    for (int t = tid; t < Bc * HDc; t += 128) {
        int b = t >> 6, dd = t & 63;
        Qs[b][dd] = qkv[(size_t)(b * Sc + i) * D3c + h * 192 + dd];
    }
    __syncthreads();

    float acc[3][Bc];
    #pragma unroll
    for (int jj = 0; jj < 3; jj++)
        #pragma unroll
        for (int b = 0; b < Bc; b++) acc[jj][b] = 0.f;
    #pragma unroll
    for (int c = 0; c < 16; c++) {
        float4 qv[Bc];
        #pragma unroll
        for (int b = 0; b < Bc; b++) qv[b] = *(const float4*)&Qs[b][c * 4];
        #pragma unroll
        for (int jj = 0; jj < 3; jj++) {
            int j = tid + jj * 128;
            float4 rv = *(const float4*)(rbase + (size_t)j * 64 + c * 4);
            #pragma unroll
            for (int b = 0; b < Bc; b++)
                acc[jj][b] += qv[b].x * rv.x + qv[b].y * rv.y +
                              qv[b].z * rv.z + qv[b].w * rv.w;
        }
    }
    #pragma unroll
    for (int jj = 0; jj < 3; jj++) {
        const int j = tid + jj * 128;
        #pragma unroll
        for (int b = 0; b < Bc; b++) {
            size_t idx = ((size_t)(b * Hc + h) * Sc + i) * Sc + j;
            L[b][j] = attn[idx] + acc[jj][b];
        }
    }
    __syncthreads();

    const int wrp = tid >> 5, lane = tid & 31;
    #pragma unroll
    for (int bb = 0; bb < 2; bb++) {
        const int b = wrp * 2 + bb;
        float v[12];
        float m = -1e30f;
        #pragma unroll
        for (int r = 0; r < 12; r++) { v[r] = L[b][lane + 32 * r]; m = fmaxf(m, v[r]); }
        #pragma unroll
        for (int o = 16; o > 0; o >>= 1) m = fmaxf(m, __shfl_xor_sync(0xffffffffu, m, o));
        float s = 0.f;
        #pragma unroll
        for (int r = 0; r < 12; r++) { v[r] = __expf(v[r] - m); s += v[r]; }
        #pragma unroll
        for (int o = 16; o > 0; o >>= 1) s += __shfl_xor_sync(0xffffffffu, s, o);
        const float inv = 1.0f / s;
        const size_t rowo = ((size_t)(b * Hc + h) * Sc + i) * Sc;
        #pragma unroll
        for (int r = 0; r < 12; r++) {
            const float val = v[r] * inv;
            attn[rowo + lane + 32 * r] = val;
            const __nv_bfloat16 hh = __float2bfloat16(val);
            ath[rowo + lane + 32 * r] = hh;
            atl[rowo + lane + 32 * r] = __float2bfloat16(val - __bfloat162float(hh));
        }
    }
}

// ---------------------------------------------------------------------------
// av HMMA: values[b,i,h*64+dd] = attn @ v, 3-pass bf16 split.
// grid (3, B*H). Output 128x64 per CTA; K=384 in 6 chunks of 64, double buffer.
// A = attn tile [128 x 64j]; B = v via ldmatrix.trans from [j,dd] rows.
// Writes bf16 hi/lo directly (input for out-proj GEMM).
// ---------------------------------------------------------------------------
#define AV_ATILE 16384          // 128 x 128B
#define AV_VTILE 8192           // 64 x 128B
#define AV_STAGE (2 * AV_ATILE + 2 * AV_VTILE)   // 48 KB
#define AV_SMEM  (2 * AV_STAGE)                  // 96 KB

__global__ __launch_bounds__(256, 2) void av_mma_kernel(
    const __nv_bfloat16* __restrict__ ath, const __nv_bfloat16* __restrict__ atl,
    const __nv_bfloat16* __restrict__ qkvh, const __nv_bfloat16* __restrict__ qkvl,
    __nv_bfloat16* __restrict__ vh_out, __nv_bfloat16* __restrict__ vl_out)
{
    extern __shared__ char smem[];
    const uint32_t sb = smem_u32(smem);
    const int tid = threadIdx.x, wid = tid >> 5, lane = tid & 31;
    const int bh = blockIdx.y, b = bh >> 4, h = bh & 15;
    const int i0 = blockIdx.x * 128;

    const __nv_bfloat16* abase_h = ath + ((size_t)bh * Sc + i0) * Sc;
    const __nv_bfloat16* abase_l = atl + ((size_t)bh * Sc + i0) * Sc;
    const __nv_bfloat16* vbase_h = qkvh + h * 192 + 128;
    const __nv_bfloat16* vbase_l = qkvl + h * 192 + 128;

    auto issue = [&](int ck) {
        if (ck >= 6) { CP_COMMIT(); return; }
        const uint32_t st = sb + (ck & 1) * AV_STAGE;
        const int j0 = ck * 64;
        for (int idx = tid; idx < 1024; idx += 256) {
            const int row = idx >> 3, c = idx & 7;
            const uint32_t sw = row * 128 + ((c ^ (row & 7)) << 4);
            CP_ASYNC16(st + sw, abase_h + (size_t)row * Sc + j0 + c * 8);
            CP_ASYNC16(st + AV_ATILE + sw, abase_l + (size_t)row * Sc + j0 + c * 8);
        }
        for (int idx = tid; idx < 512; idx += 256) {
            const int row = idx >> 3, c = idx & 7;
            const uint32_t sw = row * 128 + ((c ^ (row & 7)) << 4);
            const size_t go = (size_t)(b * Sc + j0 + row) * D3c + c * 8;
            CP_ASYNC16(st + 2 * AV_ATILE + sw, vbase_h + go);
            CP_ASYNC16(st + 2 * AV_ATILE + AV_VTILE + sw, vbase_l + go);
        }
        CP_COMMIT();
    };

    const int wm = (wid & 3) * 32;    // 4 warps over 128 rows
    const int wn = (wid >> 2) * 32;   // 2 warps over 64 cols
    const int frow = lane & 15, fc = lane >> 4;
    const int krow = (lane & 7) | ((lane & 16) >> 1);   // trans row within k16
    const int colc = (lane >> 3) & 1;                    // trans 16B col half

    float acc[2][4][4];
    #pragma unroll
    for (int i = 0; i < 2; i++)
        #pragma unroll
        for (int j = 0; j < 4; j++)
            #pragma unroll
            for (int r = 0; r < 4; r++) acc[i][j][r] = 0.f;

    issue(0);
    for (int ck = 0; ck < 6; ck++) {
        issue(ck + 1);
        CP_WAIT1();
        __syncthreads();
        const uint32_t st = sb + (ck & 1) * AV_STAGE;
        #pragma unroll
        for (int ks = 0; ks < 4; ks++) {
            uint32_t aadr[2], badr[2];
            #pragma unroll
            for (int mt = 0; mt < 2; mt++) {
                const int row = wm + mt * 16 + frow;
                aadr[mt] = row * 128 + (((2 * ks + fc) ^ (row & 7)) << 4);
            }
            #pragma unroll
            for (int bt = 0; bt < 2; bt++) {
                const int row = ks * 16 + krow;
                const int c = (wn >> 3) + bt * 2 + colc;
                badr[bt] = row * 128 + ((c ^ (row & 7)) << 4);
            }
            #pragma unroll
            for (int p = 0; p < 3; p++) {
                const uint32_t at = st + (p == 1 ? AV_ATILE : 0);
                const uint32_t vt = st + 2 * AV_ATILE + (p == 2 ? AV_VTILE : 0);
                uint32_t af[2][4], bf[2][4];
                #pragma unroll
                for (int mt = 0; mt < 2; mt++) LDSM_X4(af[mt], at + aadr[mt]);
                #pragma unroll
                for (int bt = 0; bt < 2; bt++) LDSM_X4_T(bf[bt], vt + badr[bt]);
                #pragma unroll
                for (int mt = 0; mt < 2; mt++)
                    #pragma unroll
                    for (int nt = 0; nt < 4; nt++)
                        mma_bf16(acc[mt][nt], af[mt],
                                 bf[nt >> 1][nt & 1], bf[nt >> 1][(nt & 1) + 2]);
            }
        }
        __syncthreads();
    }

    const int er = lane >> 2, ec = (lane & 3) * 2;
    #pragma unroll
    for (int mt = 0; mt < 2; mt++) {
        #pragma unroll
        for (int nt = 0; nt < 4; nt++) {
            const int row = i0 + wm + mt * 16 + er;
            const int col = h * 64 + wn + nt * 8 + ec;
            const size_t o0 = (size_t)(b * Sc + row) * Dc + col;
            const size_t o1 = (size_t)(b * Sc + row + 8) * Dc + col;
            split2(acc[mt][nt][0], acc[mt][nt][1], vh_out + o0, vl_out + o0);
            split2(acc[mt][nt][2], acc[mt][nt][3], vh_out + o1, vl_out + o1);
        }
    }
}

// ---------------------------------------------------------------------------
extern "C" void kernel_launch(void* const* d_in, const int* in_sizes, int n_in,
                              void* d_out, int out_size)
{
    const float* x     = (const float*)d_in[0];
    const float* qkv_w = (const float*)d_in[1];
    const float* qkv_b = (const float*)d_in[2];
    const float* out_w = (const float*)d_in[3];
    const float* out_b = (const float*)d_in[4];
    const float* rpe   = (const float*)d_in[5];

    float *qkvbuf, *attnscr;
    __nv_bfloat16 *ah, *al, *wqh, *wql, *woh, *wol, *qkvh, *qkvl, *ath, *atl;
    cudaGetSymbolAddress((void**)&qkvbuf, g_qkv);
    cudaGetSymbolAddress((void**)&attnscr, g_attn);
    cudaGetSymbolAddress((void**)&ah, g_ah);
    cudaGetSymbolAddress((void**)&al, g_al);
    cudaGetSymbolAddress((void**)&wqh, g_wqh);
    cudaGetSymbolAddress((void**)&wql, g_wql);
    cudaGetSymbolAddress((void**)&woh, g_woh);
    cudaGetSymbolAddress((void**)&wol, g_wol);
    cudaGetSymbolAddress((void**)&qkvh, g_qkvh);
    cudaGetSymbolAddress((void**)&qkvl, g_qkvl);
    cudaGetSymbolAddress((void**)&ath, g_ath);
    cudaGetSymbolAddress((void**)&atl, g_atl);

    float* out = (float*)d_out;
    const long OUT_E = (long)BSc * Dc;
    const long ATT_E = (long)Bc * Hc * Sc * Sc;
    float* attn = ((long)out_size >= OUT_E + ATT_E) ? (out + OUT_E) : attnscr;

    cudaFuncSetAttribute(mma_gemm_kernel,
                         cudaFuncAttributeMaxDynamicSharedMemorySize, GSMEM);
    cudaFuncSetAttribute(qk_mma_kernel,
                         cudaFuncAttributeMaxDynamicSharedMemorySize, QK_SMEM);
    cudaFuncSetAttribute(av_mma_kernel,
                         cudaFuncAttributeMaxDynamicSharedMemorySize, AV_SMEM);

    const int n4x = BSc * Dc / 4;
    split_kernel<<<(n4x + 255) / 256, 256>>>(x, ah, al, n4x);
    transpose_split_kernel<<<dim3(D3c / 32, Dc / 32), dim3(32, 8)>>>(qkv_w, wqh, wql, Dc, D3c);
    transpose_split_kernel<<<dim3(Dc / 32, Dc / 32), dim3(32, 8)>>>(out_w, woh, wol, Dc, Dc);

    // 1) qkv = x @ qkv_w + b; also emit bf16 hi/lo (q cols pre-scaled 1/8)
    mma_gemm_kernel<<<dim3(D3c / 128, BSc / 128), 256, GSMEM>>>(
        ah, al, wqh, wql, qkv_b, qkvbuf, qkvh, qkvl, 1, BSc, D3c, Dc);
    // 2) logits = (q/8) . k   (HMMA)
    qk_mma_kernel<<<dim3(3, 3, Bc * Hc), 256, QK_SMEM>>>(qkvh, qkvl, attn);
    // 3+4) rpe bias + softmax; emits attn fp32 + bf16 hi/lo
    rpe_softmax_kernel<<<Hc * Sc, 128>>>(qkvbuf, rpe, attn, ath, atl);
    // 5) values = attn @ v  (HMMA) -> bf16 hi/lo
    av_mma_kernel<<<dim3(3, Bc * Hc), 256, AV_SMEM>>>(ath, atl, qkvh, qkvl, ah, al);
    // 6) out = values @ out_w + out_b   (HMMA)
    mma_gemm_kernel<<<dim3(Dc / 128, BSc / 128), 256, GSMEM>>>(
        ah, al, woh, wol, out_b, out, nullptr, nullptr, 0, BSc, Dc, Dc);
}

// round 6
// speedup vs baseline: 1.9174x; 1.0369x over previous
#include <cuda_runtime.h>
#include <cuda_bf16.h>
#include <cstdint>

#define Bc 8
#define Sc 384
#define Dc 1024
#define Hc 16
#define HDc 64
#define D3c 3072
#define BSc 3072   // B*S

// ---------------------------------------------------------------------------
// Scratch (static device globals; no runtime allocation)
// ---------------------------------------------------------------------------
__device__ float g_attn[(size_t)Bc * Hc * Sc * Sc];   // fallback attn buffer
__device__ __align__(16) __nv_bfloat16 g_ah[(size_t)BSc * Dc];    // A hi (x, then vals)
__device__ __align__(16) __nv_bfloat16 g_al[(size_t)BSc * Dc];    // A lo
__device__ __align__(16) __nv_bfloat16 g_wqh[(size_t)D3c * Dc];   // qkv_w^T hi [N,K]
__device__ __align__(16) __nv_bfloat16 g_wql[(size_t)D3c * Dc];   // qkv_w^T lo
__device__ __align__(16) __nv_bfloat16 g_woh[(size_t)Dc * Dc];    // out_w^T hi
__device__ __align__(16) __nv_bfloat16 g_wol[(size_t)Dc * Dc];    // out_w^T lo
__device__ __align__(16) __nv_bfloat16 g_qkvh[(size_t)BSc * D3c]; // qkv hi (q pre-scaled /8)
__device__ __align__(16) __nv_bfloat16 g_qkvl[(size_t)BSc * D3c]; // qkv lo

// ---------------------------------------------------------------------------
// Baseline-PTX tensor-core helpers
// ---------------------------------------------------------------------------
__device__ __forceinline__ uint32_t smem_u32(const void* p) {
    uint32_t a;
    asm("{ .reg .u64 t; cvta.to.shared.u64 t, %1; cvt.u32.u64 %0, t; }" : "=r"(a) : "l"(p));
    return a;
}
#define CP_ASYNC16(sm, gp) \
    asm volatile("cp.async.cg.shared.global [%0], [%1], 16;" :: "r"(sm), "l"(gp))
#define CP_COMMIT() asm volatile("cp.async.commit_group;" ::: "memory")
#define CP_WAIT0()  asm volatile("cp.async.wait_group 0;" ::: "memory")
#define CP_WAIT1()  asm volatile("cp.async.wait_group 1;" ::: "memory")
#define CP_WAIT2()  asm volatile("cp.async.wait_group 2;" ::: "memory")

#define LDSM_X4(r, a) \
    asm volatile("ldmatrix.sync.aligned.m8n8.x4.shared.b16 {%0,%1,%2,%3}, [%4];" \
        : "=r"((r)[0]), "=r"((r)[1]), "=r"((r)[2]), "=r"((r)[3]) : "r"(a))
#define LDSM_X4_T(r, a) \
    asm volatile("ldmatrix.sync.aligned.m8n8.x4.trans.shared.b16 {%0,%1,%2,%3}, [%4];" \
        : "=r"((r)[0]), "=r"((r)[1]), "=r"((r)[2]), "=r"((r)[3]) : "r"(a))

__device__ __forceinline__ void mma_bf16(float* d, const uint32_t* a,
                                         uint32_t b0, uint32_t b1) {
    asm volatile(
        "mma.sync.aligned.m16n8k16.row.col.f32.bf16.bf16.f32 "
        "{%0,%1,%2,%3}, {%4,%5,%6,%7}, {%8,%9}, {%0,%1,%2,%3};"
        : "+f"(d[0]), "+f"(d[1]), "+f"(d[2]), "+f"(d[3])
        : "r"(a[0]), "r"(a[1]), "r"(a[2]), "r"(a[3]), "r"(b0), "r"(b1));
}

__device__ __forceinline__ void split2(float x, float y,
                                       __nv_bfloat16* ph, __nv_bfloat16* pl) {
    __nv_bfloat16 hx = __float2bfloat16(x), hy = __float2bfloat16(y);
    *(__nv_bfloat162*)ph = __nv_bfloat162(hx, hy);
    *(__nv_bfloat162*)pl = __nv_bfloat162(
        __float2bfloat16(x - __bfloat162float(hx)),
        __float2bfloat16(y - __bfloat162float(hy)));
}
// pack (x,y) hi halves into one bf16x2 reg; lo halves into another
__device__ __forceinline__ void pack_hilo(float x, float y,
                                          uint32_t& hi, uint32_t& lo) {
    __nv_bfloat16 hx = __float2bfloat16(x), hy = __float2bfloat16(y);
    __nv_bfloat162 h2(hx, hy);
    __nv_bfloat162 l2(__float2bfloat16(x - __bfloat162float(hx)),
                      __float2bfloat16(y - __bfloat162float(hy)));
    hi = *(uint32_t*)&h2;
    lo = *(uint32_t*)&l2;
}

// ---------------------------------------------------------------------------
// HMMA bf16-split GEMM: C = (Ah+Al)@(Bh+Bl)^T + bias
// Shared-operand pass order: Ah*Bh -> Ah*Bl -> Al*Bh  (12 LDSM / 48 MMA).
// CTA 128x128, 8 warps (64x32), K-chunk 32, 3-stage cp.async, 2 CTA/SM.
// C (fp32) and Ch/Cl (bf16 hi/lo) are each optional.
// ---------------------------------------------------------------------------
#define TILE_B 8192
#define BUF_B  (4 * TILE_B)
#define NSTAGE 3
#define GSMEM  (NSTAGE * BUF_B)   // 96 KB

__global__ __launch_bounds__(256, 2) void mma_gemm_kernel(
    const __nv_bfloat16* __restrict__ Ah, const __nv_bfloat16* __restrict__ Al,
    const __nv_bfloat16* __restrict__ Bh, const __nv_bfloat16* __restrict__ Bl,
    const float* __restrict__ bias, float* __restrict__ C,
    __nv_bfloat16* __restrict__ Ch, __nv_bfloat16* __restrict__ Cl,
    int qkv_mode, int M, int N, int K)
{
    extern __shared__ char smem[];
    const uint32_t sbase = smem_u32(smem);
    const int tid  = threadIdx.x;
    const int wid  = tid >> 5;
    const int lane = tid & 31;
    const int m0 = blockIdx.y * 128;
    const int n0 = blockIdx.x * 128;
    const int mw = (wid & 1) * 64;
    const int nw = (wid >> 1) * 32;

    const int lrow = tid >> 1;
    const int c0   = (tid & 1) * 2;
    const int sw0  = (lrow >> 1) & 3;
    const __nv_bfloat16* gAh = Ah + (size_t)(m0 + lrow) * K;
    const __nv_bfloat16* gAl = Al + (size_t)(m0 + lrow) * K;
    const __nv_bfloat16* gBh = Bh + (size_t)(n0 + lrow) * K;
    const __nv_bfloat16* gBl = Bl + (size_t)(n0 + lrow) * K;
    const uint32_t soff0 = lrow * 64 + (((c0 + 0) ^ sw0) << 4);
    const uint32_t soff1 = lrow * 64 + (((c0 + 1) ^ sw0) << 4);

    const int NK = K >> 5;

    auto issue = [&](int it) {
        if (it < NK) {
            const uint32_t tb = sbase + (it % NSTAGE) * BUF_B;
            const int k0 = it << 5;
            CP_ASYNC16(tb + 0 * TILE_B + soff0, gAh + k0 + (c0 + 0) * 8);
            CP_ASYNC16(tb + 0 * TILE_B + soff1, gAh + k0 + (c0 + 1) * 8);
            CP_ASYNC16(tb + 1 * TILE_B + soff0, gAl + k0 + (c0 + 0) * 8);
            CP_ASYNC16(tb + 1 * TILE_B + soff1, gAl + k0 + (c0 + 1) * 8);
            CP_ASYNC16(tb + 2 * TILE_B + soff0, gBh + k0 + (c0 + 0) * 8);
            CP_ASYNC16(tb + 2 * TILE_B + soff1, gBh + k0 + (c0 + 1) * 8);
            CP_ASYNC16(tb + 3 * TILE_B + soff0, gBl + k0 + (c0 + 0) * 8);
            CP_ASYNC16(tb + 3 * TILE_B + soff1, gBl + k0 + (c0 + 1) * 8);
        }
        CP_COMMIT();
    };

    const int frow = lane & 15;
    const int fc   = lane >> 4;
    auto fr_addr = [&](int rbase) -> uint32_t {
        const int row = rbase + frow;
        return (uint32_t)(row * 64 + ((fc ^ ((row >> 1) & 3)) << 4));
    };
    const uint32_t aoff = fr_addr(mw);
    const uint32_t boff = fr_addr(nw);

    float acc[4][4][4];
    #pragma unroll
    for (int i = 0; i < 4; i++)
        #pragma unroll
        for (int j = 0; j < 4; j++)
            #pragma unroll
            for (int r = 0; r < 4; r++) acc[i][j][r] = 0.f;

    issue(0); issue(1); issue(2);

    for (int it = 0; it < NK; it++) {
        CP_WAIT2();
        __syncthreads();
        const uint32_t tb = sbase + (it % NSTAGE) * BUF_B;
        #pragma unroll
        for (int ks = 0; ks < 2; ks++) {
            const uint32_t kx = ks ? 32u : 0u;
            uint32_t ahf[4][4], bhf[2][4], blf[2][4];
            #pragma unroll
            for (int mt = 0; mt < 4; mt++)
                LDSM_X4(ahf[mt], tb + ((aoff + mt * 1024) ^ kx));
            #pragma unroll
            for (int bt = 0; bt < 2; bt++)
                LDSM_X4(bhf[bt], tb + 2 * TILE_B + ((boff + bt * 1024) ^ kx));
            #pragma unroll
            for (int bt = 0; bt < 2; bt++)
                LDSM_X4(blf[bt], tb + 3 * TILE_B + ((boff + bt * 1024) ^ kx));
            // pass 0: Ah*Bh
            #pragma unroll
            for (int mt = 0; mt < 4; mt++)
                #pragma unroll
                for (int nt = 0; nt < 4; nt++)
                    mma_bf16(acc[mt][nt], ahf[mt],
                             bhf[nt >> 1][nt & 1], bhf[nt >> 1][(nt & 1) + 2]);
            // pass 1: Ah*Bl (Ah reused)
            #pragma unroll
            for (int mt = 0; mt < 4; mt++)
                #pragma unroll
                for (int nt = 0; nt < 4; nt++)
                    mma_bf16(acc[mt][nt], ahf[mt],
                             blf[nt >> 1][nt & 1], blf[nt >> 1][(nt & 1) + 2]);
            // pass 2: Al*Bh (Bh reused; Al loaded late)
            uint32_t alf[4][4];
            #pragma unroll
            for (int mt = 0; mt < 4; mt++)
                LDSM_X4(alf[mt], tb + TILE_B + ((aoff + mt * 1024) ^ kx));
            #pragma unroll
            for (int mt = 0; mt < 4; mt++)
                #pragma unroll
                for (int nt = 0; nt < 4; nt++)
                    mma_bf16(acc[mt][nt], alf[mt],
                             bhf[nt >> 1][nt & 1], bhf[nt >> 1][(nt & 1) + 2]);
        }
        __syncthreads();
        issue(it + NSTAGE);
    }

    const int er = lane >> 2;
    const int ec = (lane & 3) * 2;
    #pragma unroll
    for (int mt = 0; mt < 4; mt++) {
        #pragma unroll
        for (int nt = 0; nt < 4; nt++) {
            const int col = n0 + nw + nt * 8 + ec;
            const float bx = __ldg(&bias[col]);
            const float by = __ldg(&bias[col + 1]);
            const int r0 = m0 + mw + mt * 16 + er;
            float2 v0 = make_float2(acc[mt][nt][0] + bx, acc[mt][nt][1] + by);
            float2 v1 = make_float2(acc[mt][nt][2] + bx, acc[mt][nt][3] + by);
            if (C) {
                *(float2*)(C + (size_t)r0 * N + col) = v0;
                *(float2*)(C + (size_t)(r0 + 8) * N + col) = v1;
            }
            if (Ch) {
                const float s = (qkv_mode && (((col >> 6) % 3) == 0)) ? 0.125f : 1.0f;
                split2(v0.x * s, v0.y * s, Ch + (size_t)r0 * N + col,
                       Cl + (size_t)r0 * N + col);
                split2(v1.x * s, v1.y * s, Ch + (size_t)(r0 + 8) * N + col,
                       Cl + (size_t)(r0 + 8) * N + col);
            }
        }
    }
}

// ---------------------------------------------------------------------------
// fp32 -> bf16 hi/lo split (vectorized by 4)
// ---------------------------------------------------------------------------
__global__ __launch_bounds__(256) void split_kernel(
    const float* __restrict__ src, __nv_bfloat16* __restrict__ hi,
    __nv_bfloat16* __restrict__ lo, int n4)
{
    int i = blockIdx.x * blockDim.x + threadIdx.x;
    if (i >= n4) return;
    float4 v = ((const float4*)src)[i];
    split2(v.x, v.y, hi + 4 * (size_t)i, lo + 4 * (size_t)i);
    split2(v.z, v.w, hi + 4 * (size_t)i + 2, lo + 4 * (size_t)i + 2);
}

// ---------------------------------------------------------------------------
// W[K,N] -> Wt[N,K] with bf16 hi/lo split
// ---------------------------------------------------------------------------
__global__ __launch_bounds__(256) void transpose_split_kernel(
    const float* __restrict__ W, __nv_bfloat16* __restrict__ Th,
    __nv_bfloat16* __restrict__ Tl, int K, int N)
{
    __shared__ float t[32][33];
    const int n0 = blockIdx.x * 32, k0 = blockIdx.y * 32;
    const int tx = threadIdx.x, ty = threadIdx.y;
    #pragma unroll
    for (int r = 0; r < 4; r++)
        t[ty + 8 * r][tx] = W[(size_t)(k0 + ty + 8 * r) * N + n0 + tx];
    __syncthreads();
    #pragma unroll
    for (int r = 0; r < 4; r++) {
        float v = t[tx][ty + 8 * r];
        __nv_bfloat16 h = __float2bfloat16(v);
        __nv_bfloat16 l = __float2bfloat16(v - __bfloat162float(h));
        size_t o = (size_t)(n0 + ty + 8 * r) * K + k0 + tx;
        Th[o] = h; Tl[o] = l;
    }
}

// ---------------------------------------------------------------------------
// qk HMMA: logits[b,h,i,j] = (scaled q) . k, 3-pass bf16 split.
// ---------------------------------------------------------------------------
#define QK_SMEM (4 * 16384)

__global__ __launch_bounds__(256, 2) void qk_mma_kernel(
    const __nv_bfloat16* __restrict__ qkvh, const __nv_bfloat16* __restrict__ qkvl,
    float* __restrict__ attn)
{
    extern __shared__ char smem[];
    const uint32_t sb = smem_u32(smem);
    const int tid = threadIdx.x, wid = tid >> 5, lane = tid & 31;
    const int bh = blockIdx.z, b = bh >> 4, h = bh & 15;
    const int i0 = blockIdx.y * 128, j0 = blockIdx.x * 128;

    #pragma unroll
    for (int t = 0; t < 4; t++) {
        const __nv_bfloat16* base = (t & 1) ? qkvl : qkvh;
        const int roff = (t < 2) ? i0 : j0;
        const int coff = h * 192 + ((t < 2) ? 0 : 64);
        for (int idx = tid; idx < 1024; idx += 256) {
            const int row = idx >> 3, c = idx & 7;
            const uint32_t dst = sb + t * 16384 + row * 128 + ((c ^ (row & 7)) << 4);
            CP_ASYNC16(dst, base + (size_t)(b * Sc + roff + row) * D3c + coff + c * 8);
        }
    }
    CP_COMMIT(); CP_WAIT0();
    __syncthreads();

    const int mw = (wid & 1) * 64;
    const int nw = (wid >> 1) * 32;
    const int frow = lane & 15, fc = lane >> 4;

    float acc[4][4][4];
    #pragma unroll
    for (int i = 0; i < 4; i++)
        #pragma unroll
        for (int j = 0; j < 4; j++)
            #pragma unroll
            for (int r = 0; r < 4; r++) acc[i][j][r] = 0.f;

    #pragma unroll
    for (int ks = 0; ks < 4; ks++) {
        uint32_t aadr[4], badr[2];
        #pragma unroll
        for (int mt = 0; mt < 4; mt++) {
            const int row = mw + mt * 16 + frow;
            aadr[mt] = row * 128 + (((2 * ks + fc) ^ (row & 7)) << 4);
        }
        #pragma unroll
        for (int bt = 0; bt < 2; bt++) {
            const int row = nw + bt * 16 + frow;
            badr[bt] = row * 128 + (((2 * ks + fc) ^ (row & 7)) << 4);
        }
        uint32_t ahf[4][4], bhf[2][4], blf[2][4];
        #pragma unroll
        for (int mt = 0; mt < 4; mt++) LDSM_X4(ahf[mt], sb + aadr[mt]);
        #pragma unroll
        for (int bt = 0; bt < 2; bt++) LDSM_X4(bhf[bt], sb + 2 * 16384 + badr[bt]);
        #pragma unroll
        for (int bt = 0; bt < 2; bt++) LDSM_X4(blf[bt], sb + 3 * 16384 + badr[bt]);
        #pragma unroll
        for (int mt = 0; mt < 4; mt++)
            #pragma unroll
            for (int nt = 0; nt < 4; nt++)
                mma_bf16(acc[mt][nt], ahf[mt],
                         bhf[nt >> 1][nt & 1], bhf[nt >> 1][(nt & 1) + 2]);
        #pragma unroll
        for (int mt = 0; mt < 4; mt++)
            #pragma unroll
            for (int nt = 0; nt < 4; nt++)
                mma_bf16(acc[mt][nt], ahf[mt],
                         blf[nt >> 1][nt & 1], blf[nt >> 1][(nt & 1) + 2]);
        uint32_t alf[4][4];
        #pragma unroll
        for (int mt = 0; mt < 4; mt++) LDSM_X4(alf[mt], sb + 16384 + aadr[mt]);
        #pragma unroll
        for (int mt = 0; mt < 4; mt++)
            #pragma unroll
            for (int nt = 0; nt < 4; nt++)
                mma_bf16(acc[mt][nt], alf[mt],
                         bhf[nt >> 1][nt & 1], bhf[nt >> 1][(nt & 1) + 2]);
    }

    const int er = lane >> 2, ec = (lane & 3) * 2;
    float* ob = attn + (size_t)bh * Sc * Sc;
    #pragma unroll
    for (int mt = 0; mt < 4; mt++) {
        #pragma unroll
        for (int nt = 0; nt < 4; nt++) {
            const int r0 = i0 + mw + mt * 16 + er;
            const int col = j0 + nw + nt * 8 + ec;
            *(float2*)(ob + (size_t)r0 * Sc + col) =
                make_float2(acc[mt][nt][0], acc[mt][nt][1]);
            *(float2*)(ob + (size_t)(r0 + 8) * Sc + col) =
                make_float2(acc[mt][nt][2], acc[mt][nt][3]);
        }
    }
}

// ---------------------------------------------------------------------------
// Fused XL relative bias + row softmax (fp32 attn in/out only).
// q reconstructed from bf16 hi/lo (x8 undoes the qk pre-scale; exact pow2).
// ---------------------------------------------------------------------------
__global__ __launch_bounds__(128) void rpe_softmax_kernel(
    const __nv_bfloat16* __restrict__ qkvh, const __nv_bfloat16* __restrict__ qkvl,
    const float* __restrict__ rpe, float* __restrict__ attn)
{
    const int h = blockIdx.x / Sc;
    const int i = blockIdx.x % Sc;
    const int r0 = 384 + 24 * (i & 15) - 24 * h - (i >> 4);
    const float* rbase = rpe + (size_t)r0 * 1024;
    __shared__ float Qs[Bc][HDc];
    __shared__ float L[Bc][Sc];
    const int tid = threadIdx.x;
    for (int t = tid; t < Bc * HDc; t += 128) {
        int b = t >> 6, dd = t & 63;
        const size_t idx = (size_t)(b * Sc + i) * D3c + h * 192 + dd;
        Qs[b][dd] = (__bfloat162float(qkvh[idx]) + __bfloat162float(qkvl[idx])) * 8.f;
    }
    __syncthreads();

    float acc[3][Bc];
    #pragma unroll
    for (int jj = 0; jj < 3; jj++)
        #pragma unroll
        for (int b = 0; b < Bc; b++) acc[jj][b] = 0.f;
    #pragma unroll
    for (int c = 0; c < 16; c++) {
        float4 qv[Bc];
        #pragma unroll
        for (int b = 0; b < Bc; b++) qv[b] = *(const float4*)&Qs[b][c * 4];
        #pragma unroll
        for (int jj = 0; jj < 3; jj++) {
            int j = tid + jj * 128;
            float4 rv = *(const float4*)(rbase + (size_t)j * 64 + c * 4);
            #pragma unroll
            for (int b = 0; b < Bc; b++)
                acc[jj][b] += qv[b].x * rv.x + qv[b].y * rv.y +
                              qv[b].z * rv.z + qv[b].w * rv.w;
        }
    }
    #pragma unroll
    for (int jj = 0; jj < 3; jj++) {
        const int j = tid + jj * 128;
        #pragma unroll
        for (int b = 0; b < Bc; b++) {
            size_t idx = ((size_t)(b * Hc + h) * Sc + i) * Sc + j;
            L[b][j] = attn[idx] + acc[jj][b];
        }
    }
    __syncthreads();

    const int wrp = tid >> 5, lane = tid & 31;
    #pragma unroll
    for (int bb = 0; bb < 2; bb++) {
        const int b = wrp * 2 + bb;
        float v[12];
        float m = -1e30f;
        #pragma unroll
        for (int r = 0; r < 12; r++) { v[r] = L[b][lane + 32 * r]; m = fmaxf(m, v[r]); }
        #pragma unroll
        for (int o = 16; o > 0; o >>= 1) m = fmaxf(m, __shfl_xor_sync(0xffffffffu, m, o));
        float s = 0.f;
        #pragma unroll
        for (int r = 0; r < 12; r++) { v[r] = __expf(v[r] - m); s += v[r]; }
        #pragma unroll
        for (int o = 16; o > 0; o >>= 1) s += __shfl_xor_sync(0xffffffffu, s, o);
        const float inv = 1.0f / s;
        float* orow = attn + ((size_t)(b * Hc + h) * Sc + i) * Sc;
        #pragma unroll
        for (int r = 0; r < 12; r++) orow[lane + 32 * r] = v[r] * inv;
    }
}

// ---------------------------------------------------------------------------
// av HMMA: values = attn(fp32) @ v, 3-pass bf16 split.
// A fragments built by direct LDS.64 from the fp32 attn tile (hi/lo in regs);
// V fragments via ldmatrix.trans from qkv hi/lo. Output bf16 hi/lo.
// SMEM per stage: A fp32 128x72f (36864B swizzle-free, padded) + Vh/Vl 8KB each.
// ---------------------------------------------------------------------------
#define AV_AROW 72                         // fp32 row stride (288B, 16B-aligned, padded)
#define AV_ATILE (128 * AV_AROW * 4)       // 36864
#define AV_VTILE 8192                      // 64 x 128B
#define AV_STAGE (AV_ATILE + 2 * AV_VTILE) // 53248
#define AV_SMEM  (2 * AV_STAGE)            // 106496

__global__ __launch_bounds__(256, 2) void av_mma_kernel(
    const float* __restrict__ attn,
    const __nv_bfloat16* __restrict__ qkvh, const __nv_bfloat16* __restrict__ qkvl,
    __nv_bfloat16* __restrict__ vh_out, __nv_bfloat16* __restrict__ vl_out)
{
    extern __shared__ char smem[];
    const uint32_t sb = smem_u32(smem);
    float* sA_f = (float*)smem;
    const int tid = threadIdx.x, wid = tid >> 5, lane = tid & 31;
    const int bh = blockIdx.y, b = bh >> 4, h = bh & 15;
    const int i0 = blockIdx.x * 128;

    const float* abase = attn + ((size_t)bh * Sc + i0) * Sc;
    const __nv_bfloat16* vbase_h = qkvh + h * 192 + 128;
    const __nv_bfloat16* vbase_l = qkvl + h * 192 + 128;

    auto issue = [&](int ck) {
        if (ck >= 6) { CP_COMMIT(); return; }
        const uint32_t st = sb + (ck & 1) * AV_STAGE;
        const int j0 = ck * 64;
        // A fp32 tile: 128 rows x 16 chunks(16B)
        for (int idx = tid; idx < 2048; idx += 256) {
            const int row = idx >> 4, c = idx & 15;
            CP_ASYNC16(st + row * (AV_AROW * 4) + c * 16,
                       abase + (size_t)row * Sc + j0 + c * 4);
        }
        // V hi/lo tiles: 64 rows x 8 chunks
        for (int idx = tid; idx < 512; idx += 256) {
            const int row = idx >> 3, c = idx & 7;
            const uint32_t sw = row * 128 + ((c ^ (row & 7)) << 4);
            const size_t go = (size_t)(b * Sc + j0 + row) * D3c + c * 8;
            CP_ASYNC16(st + AV_ATILE + sw, vbase_h + go);
            CP_ASYNC16(st + AV_ATILE + AV_VTILE + sw, vbase_l + go);
        }
        CP_COMMIT();
    };

    const int wm = (wid & 3) * 32;    // 4 warps over 128 rows
    const int wn = (wid >> 2) * 32;   // 2 warps over 64 cols
    const int er = lane >> 2;         // A frag row within 8
    const int ecb = (lane & 3) * 2;   // A frag k-pair base
    const int krow = (lane & 7) | ((lane & 16) >> 1);
    const int colc = (lane >> 3) & 1;

    float acc[2][4][4];
    #pragma unroll
    for (int i = 0; i < 2; i++)
        #pragma unroll
        for (int j = 0; j < 4; j++)
            #pragma unroll
            for (int r = 0; r < 4; r++) acc[i][j][r] = 0.f;

    issue(0);
    for (int ck = 0; ck < 6; ck++) {
        issue(ck + 1);
        CP_WAIT1();
        __syncthreads();
        const int stg = (ck & 1);
        float* sA = sA_f + stg * (AV_STAGE / 4);
        const uint32_t vt_h = sb + stg * AV_STAGE + AV_ATILE;
        const uint32_t vt_l = vt_h + AV_VTILE;
        #pragma unroll
        for (int ks = 0; ks < 4; ks++) {
            // Build A hi/lo fragments from fp32 smem
            uint32_t ahf[2][4], alf[2][4];
            #pragma unroll
            for (int mt = 0; mt < 2; mt++) {
                const int r_ = wm + mt * 16 + er;
                const int cb = ks * 16 + ecb;
                float2 x0 = *(float2*)(sA + (size_t)r_ * AV_AROW + cb);
                float2 x1 = *(float2*)(sA + (size_t)(r_ + 8) * AV_AROW + cb);
                float2 x2 = *(float2*)(sA + (size_t)r_ * AV_AROW + cb + 8);
                float2 x3 = *(float2*)(sA + (size_t)(r_ + 8) * AV_AROW + cb + 8);
                pack_hilo(x0.x, x0.y, ahf[mt][0], alf[mt][0]);
                pack_hilo(x1.x, x1.y, ahf[mt][1], alf[mt][1]);
                pack_hilo(x2.x, x2.y, ahf[mt][2], alf[mt][2]);
                pack_hilo(x3.x, x3.y, ahf[mt][3], alf[mt][3]);
            }
            // V fragments
            uint32_t badr[2];
            #pragma unroll
            for (int bt = 0; bt < 2; bt++) {
                const int row = ks * 16 + krow;
                const int c = (wn >> 3) + bt * 2 + colc;
                badr[bt] = row * 128 + ((c ^ (row & 7)) << 4);
            }
            uint32_t bhf[2][4], blf[2][4];
            #pragma unroll
            for (int bt = 0; bt < 2; bt++) LDSM_X4_T(bhf[bt], vt_h + badr[bt]);
            #pragma unroll
            for (int bt = 0; bt < 2; bt++) LDSM_X4_T(blf[bt], vt_l + badr[bt]);
            // pass 0: Ah*Vh; pass 1: Al*Vh; pass 2: Ah*Vl
            #pragma unroll
            for (int mt = 0; mt < 2; mt++)
                #pragma unroll
                for (int nt = 0; nt < 4; nt++)
                    mma_bf16(acc[mt][nt], ahf[mt],
                             bhf[nt >> 1][nt & 1], bhf[nt >> 1][(nt & 1) + 2]);
            #pragma unroll
            for (int mt = 0; mt < 2; mt++)
                #pragma unroll
                for (int nt = 0; nt < 4; nt++)
                    mma_bf16(acc[mt][nt], alf[mt],
                             bhf[nt >> 1][nt & 1], bhf[nt >> 1][(nt & 1) + 2]);
            #pragma unroll
            for (int mt = 0; mt < 2; mt++)
                #pragma unroll
                for (int nt = 0; nt < 4; nt++)
                    mma_bf16(acc[mt][nt], ahf[mt],
                             blf[nt >> 1][nt & 1], blf[nt >> 1][(nt & 1) + 2]);
        }
        __syncthreads();
    }

    const int ec = (lane & 3) * 2;
    #pragma unroll
    for (int mt = 0; mt < 2; mt++) {
        #pragma unroll
        for (int nt = 0; nt < 4; nt++) {
            const int row = i0 + wm + mt * 16 + er;
            const int col = h * 64 + wn + nt * 8 + ec;
            const size_t o0 = (size_t)(b * Sc + row) * Dc + col;
            const size_t o1 = (size_t)(b * Sc + row + 8) * Dc + col;
            split2(acc[mt][nt][0], acc[mt][nt][1], vh_out + o0, vl_out + o0);
            split2(acc[mt][nt][2], acc[mt][nt][3], vh_out + o1, vl_out + o1);
        }
    }
}

// ---------------------------------------------------------------------------
extern "C" void kernel_launch(void* const* d_in, const int* in_sizes, int n_in,
                              void* d_out, int out_size)
{
    const float* x     = (const float*)d_in[0];
    const float* qkv_w = (const float*)d_in[1];
    const float* qkv_b = (const float*)d_in[2];
    const float* out_w = (const float*)d_in[3];
    const float* out_b = (const float*)d_in[4];
    const float* rpe   = (const float*)d_in[5];

    float* attnscr;
    __nv_bfloat16 *ah, *al, *wqh, *wql, *woh, *wol, *qkvh, *qkvl;
    cudaGetSymbolAddress((void**)&attnscr, g_attn);
    cudaGetSymbolAddress((void**)&ah, g_ah);
    cudaGetSymbolAddress((void**)&al, g_al);
    cudaGetSymbolAddress((void**)&wqh, g_wqh);
    cudaGetSymbolAddress((void**)&wql, g_wql);
    cudaGetSymbolAddress((void**)&woh, g_woh);
    cudaGetSymbolAddress((void**)&wol, g_wol);
    cudaGetSymbolAddress((void**)&qkvh, g_qkvh);
    cudaGetSymbolAddress((void**)&qkvl, g_qkvl);

    float* out = (float*)d_out;
    const long OUT_E = (long)BSc * Dc;
    const long ATT_E = (long)Bc * Hc * Sc * Sc;
    float* attn = ((long)out_size >= OUT_E + ATT_E) ? (out + OUT_E) : attnscr;

    cudaFuncSetAttribute(mma_gemm_kernel,
                         cudaFuncAttributeMaxDynamicSharedMemorySize, GSMEM);
    cudaFuncSetAttribute(qk_mma_kernel,
                         cudaFuncAttributeMaxDynamicSharedMemorySize, QK_SMEM);
    cudaFuncSetAttribute(av_mma_kernel,
                         cudaFuncAttributeMaxDynamicSharedMemorySize, AV_SMEM);

    const int n4x = BSc * Dc / 4;
    split_kernel<<<(n4x + 255) / 256, 256>>>(x, ah, al, n4x);
    transpose_split_kernel<<<dim3(D3c / 32, Dc / 32), dim3(32, 8)>>>(qkv_w, wqh, wql, Dc, D3c);
    transpose_split_kernel<<<dim3(Dc / 32, Dc / 32), dim3(32, 8)>>>(out_w, woh, wol, Dc, Dc);

    // 1) qkv: emit ONLY bf16 hi/lo (q cols pre-scaled 1/8)
    mma_gemm_kernel<<<dim3(D3c / 128, BSc / 128), 256, GSMEM>>>(
        ah, al, wqh, wql, qkv_b, nullptr, qkvh, qkvl, 1, BSc, D3c, Dc);
    // 2) logits = (q/8) . k
    qk_mma_kernel<<<dim3(3, 3, Bc * Hc), 256, QK_SMEM>>>(qkvh, qkvl, attn);
    // 3+4) rpe bias + softmax (fp32 attn only)
    rpe_softmax_kernel<<<Hc * Sc, 128>>>(qkvh, qkvl, rpe, attn);
    // 5) values = attn @ v -> bf16 hi/lo
    av_mma_kernel<<<dim3(3, Bc * Hc), 256, AV_SMEM>>>(attn, qkvh, qkvl, ah, al);
    // 6) out = values @ out_w + out_b (fp32 out only)
    mma_gemm_kernel<<<dim3(Dc / 128, BSc / 128), 256, GSMEM>>>(
        ah, al, woh, wol, out_b, out, nullptr, nullptr, 0, BSc, Dc, Dc);
}

// round 7
// speedup vs baseline: 1.9456x; 1.0147x over previous
#include <cuda_runtime.h>
#include <cuda_bf16.h>
#include <cstdint>

#define Bc 8
#define Sc 384
#define Dc 1024
#define Hc 16
#define HDc 64
#define D3c 3072
#define BSc 3072   // B*S

// ---------------------------------------------------------------------------
// Scratch (static device globals; no runtime allocation)
// ---------------------------------------------------------------------------
__device__ float g_attn[(size_t)Bc * Hc * Sc * Sc];   // fallback attn buffer
__device__ __align__(16) __nv_bfloat16 g_ah[(size_t)BSc * Dc];    // A hi (x, then vals)
__device__ __align__(16) __nv_bfloat16 g_al[(size_t)BSc * Dc];    // A lo
__device__ __align__(16) __nv_bfloat16 g_wqh[(size_t)D3c * Dc];   // qkv_w^T hi [N,K]
__device__ __align__(16) __nv_bfloat16 g_wql[(size_t)D3c * Dc];   // qkv_w^T lo
__device__ __align__(16) __nv_bfloat16 g_woh[(size_t)Dc * Dc];    // out_w^T hi
__device__ __align__(16) __nv_bfloat16 g_wol[(size_t)Dc * Dc];    // out_w^T lo
__device__ __align__(16) __nv_bfloat16 g_qkvh[(size_t)BSc * D3c]; // qkv hi (q pre-scaled /8)
__device__ __align__(16) __nv_bfloat16 g_qkvl[(size_t)BSc * D3c]; // qkv lo

// ---------------------------------------------------------------------------
// Baseline-PTX helpers
// ---------------------------------------------------------------------------
__device__ __forceinline__ uint32_t smem_u32(const void* p) {
    uint32_t a;
    asm("{ .reg .u64 t; cvta.to.shared.u64 t, %1; cvt.u32.u64 %0, t; }" : "=r"(a) : "l"(p));
    return a;
}
#define CP_ASYNC16(sm, gp) \
    asm volatile("cp.async.cg.shared.global [%0], [%1], 16;" :: "r"(sm), "l"(gp))
#define CP_COMMIT() asm volatile("cp.async.commit_group;" ::: "memory")
#define CP_WAIT0()  asm volatile("cp.async.wait_group 0;" ::: "memory")
#define CP_WAIT1()  asm volatile("cp.async.wait_group 1;" ::: "memory")
#define CP_WAIT2()  asm volatile("cp.async.wait_group 2;" ::: "memory")

#define LDSM_X4(r, a) \
    asm volatile("ldmatrix.sync.aligned.m8n8.x4.shared.b16 {%0,%1,%2,%3}, [%4];" \
        : "=r"((r)[0]), "=r"((r)[1]), "=r"((r)[2]), "=r"((r)[3]) : "r"(a))
#define LDSM_X4_T(r, a) \
    asm volatile("ldmatrix.sync.aligned.m8n8.x4.trans.shared.b16 {%0,%1,%2,%3}, [%4];" \
        : "=r"((r)[0]), "=r"((r)[1]), "=r"((r)[2]), "=r"((r)[3]) : "r"(a))

__device__ __forceinline__ void mma_bf16(float* d, const uint32_t* a,
                                         uint32_t b0, uint32_t b1) {
    asm volatile(
        "mma.sync.aligned.m16n8k16.row.col.f32.bf16.bf16.f32 "
        "{%0,%1,%2,%3}, {%4,%5,%6,%7}, {%8,%9}, {%0,%1,%2,%3};"
        : "+f"(d[0]), "+f"(d[1]), "+f"(d[2]), "+f"(d[3])
        : "r"(a[0]), "r"(a[1]), "r"(a[2]), "r"(a[3]), "r"(b0), "r"(b1));
}

// packed f32x2 (Blackwell FFMA2; baseline sm_100+ PTX)
__device__ __forceinline__ unsigned long long packf2(float x, float y) {
    unsigned long long r;
    asm("mov.b64 %0, {%1, %2};" : "=l"(r) : "f"(x), "f"(y));
    return r;
}
#define FFMA2(acc, a, b) \
    asm("fma.rn.f32x2 %0, %1, %2, %0;" : "+l"(acc) : "l"(a), "l"(b))
__device__ __forceinline__ void unpackf2(unsigned long long v, float& lo, float& hi) {
    asm("mov.b64 {%0, %1}, %2;" : "=f"(lo), "=f"(hi) : "l"(v));
}

__device__ __forceinline__ void split2(float x, float y,
                                       __nv_bfloat16* ph, __nv_bfloat16* pl) {
    __nv_bfloat16 hx = __float2bfloat16(x), hy = __float2bfloat16(y);
    *(__nv_bfloat162*)ph = __nv_bfloat162(hx, hy);
    *(__nv_bfloat162*)pl = __nv_bfloat162(
        __float2bfloat16(x - __bfloat162float(hx)),
        __float2bfloat16(y - __bfloat162float(hy)));
}
__device__ __forceinline__ void pack_hilo(float x, float y,
                                          uint32_t& hi, uint32_t& lo) {
    __nv_bfloat16 hx = __float2bfloat16(x), hy = __float2bfloat16(y);
    __nv_bfloat162 h2(hx, hy);
    __nv_bfloat162 l2(__float2bfloat16(x - __bfloat162float(hx)),
                      __float2bfloat16(y - __bfloat162float(hy)));
    hi = *(uint32_t*)&h2;
    lo = *(uint32_t*)&l2;
}

// ---------------------------------------------------------------------------
// HMMA bf16-split GEMM: C = (Ah+Al)@(Bh+Bl)^T + bias
// Pass order with interleaved LDSM: Ah,Bh -> p0 -> Bl -> p1(Ah*Bl) -> Al -> p2(Al*Bh)
// ---------------------------------------------------------------------------
#define TILE_B 8192
#define BUF_B  (4 * TILE_B)
#define NSTAGE 3
#define GSMEM  (NSTAGE * BUF_B)   // 96 KB

__global__ __launch_bounds__(256, 2) void mma_gemm_kernel(
    const __nv_bfloat16* __restrict__ Ah, const __nv_bfloat16* __restrict__ Al,
    const __nv_bfloat16* __restrict__ Bh, const __nv_bfloat16* __restrict__ Bl,
    const float* __restrict__ bias, float* __restrict__ C,
    __nv_bfloat16* __restrict__ Ch, __nv_bfloat16* __restrict__ Cl,
    int qkv_mode, int M, int N, int K)
{
    extern __shared__ char smem[];
    const uint32_t sbase = smem_u32(smem);
    const int tid  = threadIdx.x;
    const int wid  = tid >> 5;
    const int lane = tid & 31;
    const int m0 = blockIdx.y * 128;
    const int n0 = blockIdx.x * 128;
    const int mw = (wid & 1) * 64;
    const int nw = (wid >> 1) * 32;

    const int lrow = tid >> 1;
    const int c0   = (tid & 1) * 2;
    const int sw0  = (lrow >> 1) & 3;
    const __nv_bfloat16* gAh = Ah + (size_t)(m0 + lrow) * K;
    const __nv_bfloat16* gAl = Al + (size_t)(m0 + lrow) * K;
    const __nv_bfloat16* gBh = Bh + (size_t)(n0 + lrow) * K;
    const __nv_bfloat16* gBl = Bl + (size_t)(n0 + lrow) * K;
    const uint32_t soff0 = lrow * 64 + (((c0 + 0) ^ sw0) << 4);
    const uint32_t soff1 = lrow * 64 + (((c0 + 1) ^ sw0) << 4);

    const int NK = K >> 5;

    auto issue = [&](int it) {
        if (it < NK) {
            const uint32_t tb = sbase + (it % NSTAGE) * BUF_B;
            const int k0 = it << 5;
            CP_ASYNC16(tb + 0 * TILE_B + soff0, gAh + k0 + (c0 + 0) * 8);
            CP_ASYNC16(tb + 0 * TILE_B + soff1, gAh + k0 + (c0 + 1) * 8);
            CP_ASYNC16(tb + 1 * TILE_B + soff0, gAl + k0 + (c0 + 0) * 8);
            CP_ASYNC16(tb + 1 * TILE_B + soff1, gAl + k0 + (c0 + 1) * 8);
            CP_ASYNC16(tb + 2 * TILE_B + soff0, gBh + k0 + (c0 + 0) * 8);
            CP_ASYNC16(tb + 2 * TILE_B + soff1, gBh + k0 + (c0 + 1) * 8);
            CP_ASYNC16(tb + 3 * TILE_B + soff0, gBl + k0 + (c0 + 0) * 8);
            CP_ASYNC16(tb + 3 * TILE_B + soff1, gBl + k0 + (c0 + 1) * 8);
        }
        CP_COMMIT();
    };

    const int frow = lane & 15;
    const int fc   = lane >> 4;
    auto fr_addr = [&](int rbase) -> uint32_t {
        const int row = rbase + frow;
        return (uint32_t)(row * 64 + ((fc ^ ((row >> 1) & 3)) << 4));
    };
    const uint32_t aoff = fr_addr(mw);
    const uint32_t boff = fr_addr(nw);

    float acc[4][4][4];
    #pragma unroll
    for (int i = 0; i < 4; i++)
        #pragma unroll
        for (int j = 0; j < 4; j++)
            #pragma unroll
            for (int r = 0; r < 4; r++) acc[i][j][r] = 0.f;

    issue(0); issue(1); issue(2);

    for (int it = 0; it < NK; it++) {
        CP_WAIT2();
        __syncthreads();
        const uint32_t tb = sbase + (it % NSTAGE) * BUF_B;
        #pragma unroll
        for (int ks = 0; ks < 2; ks++) {
            const uint32_t kx = ks ? 32u : 0u;
            uint32_t ahf[4][4], bhf[2][4];
            #pragma unroll
            for (int mt = 0; mt < 4; mt++)
                LDSM_X4(ahf[mt], tb + ((aoff + mt * 1024) ^ kx));
            #pragma unroll
            for (int bt = 0; bt < 2; bt++)
                LDSM_X4(bhf[bt], tb + 2 * TILE_B + ((boff + bt * 1024) ^ kx));
            // pass 0: Ah*Bh
            #pragma unroll
            for (int mt = 0; mt < 4; mt++)
                #pragma unroll
                for (int nt = 0; nt < 4; nt++)
                    mma_bf16(acc[mt][nt], ahf[mt],
                             bhf[nt >> 1][nt & 1], bhf[nt >> 1][(nt & 1) + 2]);
            // load Bl while pass0 drains
            uint32_t blf[2][4];
            #pragma unroll
            for (int bt = 0; bt < 2; bt++)
                LDSM_X4(blf[bt], tb + 3 * TILE_B + ((boff + bt * 1024) ^ kx));
            // pass 1: Ah*Bl
            #pragma unroll
            for (int mt = 0; mt < 4; mt++)
                #pragma unroll
                for (int nt = 0; nt < 4; nt++)
                    mma_bf16(acc[mt][nt], ahf[mt],
                             blf[nt >> 1][nt & 1], blf[nt >> 1][(nt & 1) + 2]);
            // load Al while pass1 drains
            uint32_t alf[4][4];
            #pragma unroll
            for (int mt = 0; mt < 4; mt++)
                LDSM_X4(alf[mt], tb + TILE_B + ((aoff + mt * 1024) ^ kx));
            // pass 2: Al*Bh
            #pragma unroll
            for (int mt = 0; mt < 4; mt++)
                #pragma unroll
                for (int nt = 0; nt < 4; nt++)
                    mma_bf16(acc[mt][nt], alf[mt],
                             bhf[nt >> 1][nt & 1], bhf[nt >> 1][(nt & 1) + 2]);
        }
        __syncthreads();
        issue(it + NSTAGE);
    }

    const int er = lane >> 2;
    const int ec = (lane & 3) * 2;
    #pragma unroll
    for (int mt = 0; mt < 4; mt++) {
        #pragma unroll
        for (int nt = 0; nt < 4; nt++) {
            const int col = n0 + nw + nt * 8 + ec;
            const float bx = __ldg(&bias[col]);
            const float by = __ldg(&bias[col + 1]);
            const int r0 = m0 + mw + mt * 16 + er;
            float2 v0 = make_float2(acc[mt][nt][0] + bx, acc[mt][nt][1] + by);
            float2 v1 = make_float2(acc[mt][nt][2] + bx, acc[mt][nt][3] + by);
            if (C) {
                *(float2*)(C + (size_t)r0 * N + col) = v0;
                *(float2*)(C + (size_t)(r0 + 8) * N + col) = v1;
            }
            if (Ch) {
                const float s = (qkv_mode && (((col >> 6) % 3) == 0)) ? 0.125f : 1.0f;
                split2(v0.x * s, v0.y * s, Ch + (size_t)r0 * N + col,
                       Cl + (size_t)r0 * N + col);
                split2(v1.x * s, v1.y * s, Ch + (size_t)(r0 + 8) * N + col,
                       Cl + (size_t)(r0 + 8) * N + col);
            }
        }
    }
}

// ---------------------------------------------------------------------------
// fp32 -> bf16 hi/lo split (vectorized by 4)
// ---------------------------------------------------------------------------
__global__ __launch_bounds__(256) void split_kernel(
    const float* __restrict__ src, __nv_bfloat16* __restrict__ hi,
    __nv_bfloat16* __restrict__ lo, int n4)
{
    int i = blockIdx.x * blockDim.x + threadIdx.x;
    if (i >= n4) return;
    float4 v = ((const float4*)src)[i];
    split2(v.x, v.y, hi + 4 * (size_t)i, lo + 4 * (size_t)i);
    split2(v.z, v.w, hi + 4 * (size_t)i + 2, lo + 4 * (size_t)i + 2);
}

// ---------------------------------------------------------------------------
// W[K,N] -> Wt[N,K] with bf16 hi/lo split
// ---------------------------------------------------------------------------
__global__ __launch_bounds__(256) void transpose_split_kernel(
    const float* __restrict__ W, __nv_bfloat16* __restrict__ Th,
    __nv_bfloat16* __restrict__ Tl, int K, int N)
{
    __shared__ float t[32][33];
    const int n0 = blockIdx.x * 32, k0 = blockIdx.y * 32;
    const int tx = threadIdx.x, ty = threadIdx.y;
    #pragma unroll
    for (int r = 0; r < 4; r++)
        t[ty + 8 * r][tx] = W[(size_t)(k0 + ty + 8 * r) * N + n0 + tx];
    __syncthreads();
    #pragma unroll
    for (int r = 0; r < 4; r++) {
        float v = t[tx][ty + 8 * r];
        __nv_bfloat16 h = __float2bfloat16(v);
        __nv_bfloat16 l = __float2bfloat16(v - __bfloat162float(h));
        size_t o = (size_t)(n0 + ty + 8 * r) * K + k0 + tx;
        Th[o] = h; Tl[o] = l;
    }
}

// ---------------------------------------------------------------------------
// qk HMMA: logits = (scaled q).k, 3-pass bf16 split, interleaved LDSM.
// ---------------------------------------------------------------------------
#define QK_SMEM (4 * 16384)

__global__ __launch_bounds__(256, 2) void qk_mma_kernel(
    const __nv_bfloat16* __restrict__ qkvh, const __nv_bfloat16* __restrict__ qkvl,
    float* __restrict__ attn)
{
    extern __shared__ char smem[];
    const uint32_t sb = smem_u32(smem);
    const int tid = threadIdx.x, wid = tid >> 5, lane = tid & 31;
    const int bh = blockIdx.z, b = bh >> 4, h = bh & 15;
    const int i0 = blockIdx.y * 128, j0 = blockIdx.x * 128;

    #pragma unroll
    for (int t = 0; t < 4; t++) {
        const __nv_bfloat16* base = (t & 1) ? qkvl : qkvh;
        const int roff = (t < 2) ? i0 : j0;
        const int coff = h * 192 + ((t < 2) ? 0 : 64);
        for (int idx = tid; idx < 1024; idx += 256) {
            const int row = idx >> 3, c = idx & 7;
            const uint32_t dst = sb + t * 16384 + row * 128 + ((c ^ (row & 7)) << 4);
            CP_ASYNC16(dst, base + (size_t)(b * Sc + roff + row) * D3c + coff + c * 8);
        }
    }
    CP_COMMIT(); CP_WAIT0();
    __syncthreads();

    const int mw = (wid & 1) * 64;
    const int nw = (wid >> 1) * 32;
    const int frow = lane & 15, fc = lane >> 4;

    float acc[4][4][4];
    #pragma unroll
    for (int i = 0; i < 4; i++)
        #pragma unroll
        for (int j = 0; j < 4; j++)
            #pragma unroll
            for (int r = 0; r < 4; r++) acc[i][j][r] = 0.f;

    #pragma unroll
    for (int ks = 0; ks < 4; ks++) {
        uint32_t aadr[4], badr[2];
        #pragma unroll
        for (int mt = 0; mt < 4; mt++) {
            const int row = mw + mt * 16 + frow;
            aadr[mt] = row * 128 + (((2 * ks + fc) ^ (row & 7)) << 4);
        }
        #pragma unroll
        for (int bt = 0; bt < 2; bt++) {
            const int row = nw + bt * 16 + frow;
            badr[bt] = row * 128 + (((2 * ks + fc) ^ (row & 7)) << 4);
        }
        uint32_t ahf[4][4], bhf[2][4];
        #pragma unroll
        for (int mt = 0; mt < 4; mt++) LDSM_X4(ahf[mt], sb + aadr[mt]);
        #pragma unroll
        for (int bt = 0; bt < 2; bt++) LDSM_X4(bhf[bt], sb + 2 * 16384 + badr[bt]);
        #pragma unroll
        for (int mt = 0; mt < 4; mt++)
            #pragma unroll
            for (int nt = 0; nt < 4; nt++)
                mma_bf16(acc[mt][nt], ahf[mt],
                         bhf[nt >> 1][nt & 1], bhf[nt >> 1][(nt & 1) + 2]);
        uint32_t blf[2][4];
        #pragma unroll
        for (int bt = 0; bt < 2; bt++) LDSM_X4(blf[bt], sb + 3 * 16384 + badr[bt]);
        #pragma unroll
        for (int mt = 0; mt < 4; mt++)
            #pragma unroll
            for (int nt = 0; nt < 4; nt++)
                mma_bf16(acc[mt][nt], ahf[mt],
                         blf[nt >> 1][nt & 1], blf[nt >> 1][(nt & 1) + 2]);
        uint32_t alf[4][4];
        #pragma unroll
        for (int mt = 0; mt < 4; mt++) LDSM_X4(alf[mt], sb + 16384 + aadr[mt]);
        #pragma unroll
        for (int mt = 0; mt < 4; mt++)
            #pragma unroll
            for (int nt = 0; nt < 4; nt++)
                mma_bf16(acc[mt][nt], alf[mt],
                         bhf[nt >> 1][nt & 1], bhf[nt >> 1][(nt & 1) + 2]);
    }

    const int er = lane >> 2, ec = (lane & 3) * 2;
    float* ob = attn + (size_t)bh * Sc * Sc;
    #pragma unroll
    for (int mt = 0; mt < 4; mt++) {
        #pragma unroll
        for (int nt = 0; nt < 4; nt++) {
            const int r0 = i0 + mw + mt * 16 + er;
            const int col = j0 + nw + nt * 8 + ec;
            *(float2*)(ob + (size_t)r0 * Sc + col) =
                make_float2(acc[mt][nt][0], acc[mt][nt][1]);
            *(float2*)(ob + (size_t)(r0 + 8) * Sc + col) =
                make_float2(acc[mt][nt][2], acc[mt][nt][3]);
        }
    }
}

// ---------------------------------------------------------------------------
// Fused XL relative bias + row softmax, packed f32x2 FMA accumulation.
// q pairs (b even, b odd) packed into u64 smem; each slab value packed once
// and driven through 4 FFMA2 (covers all 8 batches in half the FMA issues).
// ---------------------------------------------------------------------------
__global__ __launch_bounds__(128) void rpe_softmax_kernel(
    const __nv_bfloat16* __restrict__ qkvh, const __nv_bfloat16* __restrict__ qkvl,
    const float* __restrict__ rpe, float* __restrict__ attn)
{
    const int h = blockIdx.x / Sc;
    const int i = blockIdx.x % Sc;
    const int r0 = 384 + 24 * (i & 15) - 24 * h - (i >> 4);
    const float* rbase = rpe + (size_t)r0 * 1024;
    __shared__ unsigned long long Qp[256];   // [dd*4 + p] = (q[2p][dd], q[2p+1][dd])
    __shared__ float L[Bc][Sc];
    const int tid = threadIdx.x;
    for (int t = tid; t < 256; t += 128) {
        const int p = t & 3, dd = t >> 2;
        const size_t i0x = (size_t)((2 * p) * Sc + i) * D3c + h * 192 + dd;
        const size_t i1x = (size_t)((2 * p + 1) * Sc + i) * D3c + h * 192 + dd;
        const float q0 = (__bfloat162float(qkvh[i0x]) + __bfloat162float(qkvl[i0x])) * 8.f;
        const float q1 = (__bfloat162float(qkvh[i1x]) + __bfloat162float(qkvl[i1x])) * 8.f;
        Qp[t] = packf2(q0, q1);
    }
    __syncthreads();

    unsigned long long acc2[3][4];
    #pragma unroll
    for (int jj = 0; jj < 3; jj++)
        #pragma unroll
        for (int p = 0; p < 4; p++) acc2[jj][p] = 0ull;

    #pragma unroll
    for (int c = 0; c < 16; c++) {
        unsigned long long qp[4][4];
        #pragma unroll
        for (int d2 = 0; d2 < 4; d2++)
            #pragma unroll
            for (int p = 0; p < 4; p++)
                qp[d2][p] = Qp[(c * 4 + d2) * 4 + p];
        #pragma unroll
        for (int jj = 0; jj < 3; jj++) {
            const int j = tid + jj * 128;
            const float4 rv = *(const float4*)(rbase + (size_t)j * 64 + c * 4);
            const unsigned long long s0 = packf2(rv.x, rv.x);
            const unsigned long long s1 = packf2(rv.y, rv.y);
            const unsigned long long s2 = packf2(rv.z, rv.z);
            const unsigned long long s3 = packf2(rv.w, rv.w);
            #pragma unroll
            for (int p = 0; p < 4; p++) {
                FFMA2(acc2[jj][p], qp[0][p], s0);
                FFMA2(acc2[jj][p], qp[1][p], s1);
                FFMA2(acc2[jj][p], qp[2][p], s2);
                FFMA2(acc2[jj][p], qp[3][p], s3);
            }
        }
    }
    #pragma unroll
    for (int jj = 0; jj < 3; jj++) {
        const int j = tid + jj * 128;
        #pragma unroll
        for (int p = 0; p < 4; p++) {
            float lo, hi;
            unpackf2(acc2[jj][p], lo, hi);
            const int b0 = 2 * p, b1 = 2 * p + 1;
            L[b0][j] = attn[((size_t)(b0 * Hc + h) * Sc + i) * Sc + j] + lo;
            L[b1][j] = attn[((size_t)(b1 * Hc + h) * Sc + i) * Sc + j] + hi;
        }
    }
    __syncthreads();

    const int wrp = tid >> 5, lane = tid & 31;
    #pragma unroll
    for (int bb = 0; bb < 2; bb++) {
        const int b = wrp * 2 + bb;
        float v[12];
        float m = -1e30f;
        #pragma unroll
        for (int r = 0; r < 12; r++) { v[r] = L[b][lane + 32 * r]; m = fmaxf(m, v[r]); }
        #pragma unroll
        for (int o = 16; o > 0; o >>= 1) m = fmaxf(m, __shfl_xor_sync(0xffffffffu, m, o));
        float s = 0.f;
        #pragma unroll
        for (int r = 0; r < 12; r++) { v[r] = __expf(v[r] - m); s += v[r]; }
        #pragma unroll
        for (int o = 16; o > 0; o >>= 1) s += __shfl_xor_sync(0xffffffffu, s, o);
        const float inv = 1.0f / s;
        float* orow = attn + ((size_t)(b * Hc + h) * Sc + i) * Sc;
        #pragma unroll
        for (int r = 0; r < 12; r++) orow[lane + 32 * r] = v[r] * inv;
    }
}

// ---------------------------------------------------------------------------
// av HMMA: values = attn(fp32) @ v, 3-pass bf16 split. (unchanged from R6)
// ---------------------------------------------------------------------------
#define AV_AROW 72
#define AV_ATILE (128 * AV_AROW * 4)
#define AV_VTILE 8192
#define AV_STAGE (AV_ATILE + 2 * AV_VTILE)
#define AV_SMEM  (2 * AV_STAGE)

__global__ __launch_bounds__(256, 2) void av_mma_kernel(
    const float* __restrict__ attn,
    const __nv_bfloat16* __restrict__ qkvh, const __nv_bfloat16* __restrict__ qkvl,
    __nv_bfloat16* __restrict__ vh_out, __nv_bfloat16* __restrict__ vl_out)
{
    extern __shared__ char smem[];
    const uint32_t sb = smem_u32(smem);
    float* sA_f = (float*)smem;
    const int tid = threadIdx.x, wid = tid >> 5, lane = tid & 31;
    const int bh = blockIdx.y, b = bh >> 4, h = bh & 15;
    const int i0 = blockIdx.x * 128;

    const float* abase = attn + ((size_t)bh * Sc + i0) * Sc;
    const __nv_bfloat16* vbase_h = qkvh + h * 192 + 128;
    const __nv_bfloat16* vbase_l = qkvl + h * 192 + 128;

    auto issue = [&](int ck) {
        if (ck >= 6) { CP_COMMIT(); return; }
        const uint32_t st = sb + (ck & 1) * AV_STAGE;
        const int j0 = ck * 64;
        for (int idx = tid; idx < 2048; idx += 256) {
            const int row = idx >> 4, c = idx & 15;
            CP_ASYNC16(st + row * (AV_AROW * 4) + c * 16,
                       abase + (size_t)row * Sc + j0 + c * 4);
        }
        for (int idx = tid; idx < 512; idx += 256) {
            const int row = idx >> 3, c = idx & 7;
            const uint32_t sw = row * 128 + ((c ^ (row & 7)) << 4);
            const size_t go = (size_t)(b * Sc + j0 + row) * D3c + c * 8;
            CP_ASYNC16(st + AV_ATILE + sw, vbase_h + go);
            CP_ASYNC16(st + AV_ATILE + AV_VTILE + sw, vbase_l + go);
        }
        CP_COMMIT();
    };

    const int wm = (wid & 3) * 32;
    const int wn = (wid >> 2) * 32;
    const int er = lane >> 2;
    const int ecb = (lane & 3) * 2;
    const int krow = (lane & 7) | ((lane & 16) >> 1);
    const int colc = (lane >> 3) & 1;

    float acc[2][4][4];
    #pragma unroll
    for (int i = 0; i < 2; i++)
        #pragma unroll
        for (int j = 0; j < 4; j++)
            #pragma unroll
            for (int r = 0; r < 4; r++) acc[i][j][r] = 0.f;

    issue(0);
    for (int ck = 0; ck < 6; ck++) {
        issue(ck + 1);
        CP_WAIT1();
        __syncthreads();
        const int stg = (ck & 1);
        float* sA = sA_f + stg * (AV_STAGE / 4);
        const uint32_t vt_h = sb + stg * AV_STAGE + AV_ATILE;
        const uint32_t vt_l = vt_h + AV_VTILE;
        #pragma unroll
        for (int ks = 0; ks < 4; ks++) {
            uint32_t ahf[2][4], alf[2][4];
            #pragma unroll
            for (int mt = 0; mt < 2; mt++) {
                const int r_ = wm + mt * 16 + er;
                const int cb = ks * 16 + ecb;
                float2 x0 = *(float2*)(sA + (size_t)r_ * AV_AROW + cb);
                float2 x1 = *(float2*)(sA + (size_t)(r_ + 8) * AV_AROW + cb);
                float2 x2 = *(float2*)(sA + (size_t)r_ * AV_AROW + cb + 8);
                float2 x3 = *(float2*)(sA + (size_t)(r_ + 8) * AV_AROW + cb + 8);
                pack_hilo(x0.x, x0.y, ahf[mt][0], alf[mt][0]);
                pack_hilo(x1.x, x1.y, ahf[mt][1], alf[mt][1]);
                pack_hilo(x2.x, x2.y, ahf[mt][2], alf[mt][2]);
                pack_hilo(x3.x, x3.y, ahf[mt][3], alf[mt][3]);
            }
            uint32_t badr[2];
            #pragma unroll
            for (int bt = 0; bt < 2; bt++) {
                const int row = ks * 16 + krow;
                const int c = (wn >> 3) + bt * 2 + colc;
                badr[bt] = row * 128 + ((c ^ (row & 7)) << 4);
            }
            uint32_t bhf[2][4], blf[2][4];
            #pragma unroll
            for (int bt = 0; bt < 2; bt++) LDSM_X4_T(bhf[bt], vt_h + badr[bt]);
            #pragma unroll
            for (int bt = 0; bt < 2; bt++) LDSM_X4_T(blf[bt], vt_l + badr[bt]);
            #pragma unroll
            for (int mt = 0; mt < 2; mt++)
                #pragma unroll
                for (int nt = 0; nt < 4; nt++)
                    mma_bf16(acc[mt][nt], ahf[mt],
                             bhf[nt >> 1][nt & 1], bhf[nt >> 1][(nt & 1) + 2]);
            #pragma unroll
            for (int mt = 0; mt < 2; mt++)
                #pragma unroll
                for (int nt = 0; nt < 4; nt++)
                    mma_bf16(acc[mt][nt], alf[mt],
                             bhf[nt >> 1][nt & 1], bhf[nt >> 1][(nt & 1) + 2]);
            #pragma unroll
            for (int mt = 0; mt < 2; mt++)
                #pragma unroll
                for (int nt = 0; nt < 4; nt++)
                    mma_bf16(acc[mt][nt], ahf[mt],
                             blf[nt >> 1][nt & 1], blf[nt >> 1][(nt & 1) + 2]);
        }
        __syncthreads();
    }

    const int ec = (lane & 3) * 2;
    #pragma unroll
    for (int mt = 0; mt < 2; mt++) {
        #pragma unroll
        for (int nt = 0; nt < 4; nt++) {
            const int row = i0 + wm + mt * 16 + er;
            const int col = h * 64 + wn + nt * 8 + ec;
            const size_t o0 = (size_t)(b * Sc + row) * Dc + col;
            const size_t o1 = (size_t)(b * Sc + row + 8) * Dc + col;
            split2(acc[mt][nt][0], acc[mt][nt][1], vh_out + o0, vl_out + o0);
            split2(acc[mt][nt][2], acc[mt][nt][3], vh_out + o1, vl_out + o1);
        }
    }
}

// ---------------------------------------------------------------------------
extern "C" void kernel_launch(void* const* d_in, const int* in_sizes, int n_in,
                              void* d_out, int out_size)
{
    const float* x     = (const float*)d_in[0];
    const float* qkv_w = (const float*)d_in[1];
    const float* qkv_b = (const float*)d_in[2];
    const float* out_w = (const float*)d_in[3];
    const float* out_b = (const float*)d_in[4];
    const float* rpe   = (const float*)d_in[5];

    float* attnscr;
    __nv_bfloat16 *ah, *al, *wqh, *wql, *woh, *wol, *qkvh, *qkvl;
    cudaGetSymbolAddress((void**)&attnscr, g_attn);
    cudaGetSymbolAddress((void**)&ah, g_ah);
    cudaGetSymbolAddress((void**)&al, g_al);
    cudaGetSymbolAddress((void**)&wqh, g_wqh);
    cudaGetSymbolAddress((void**)&wql, g_wql);
    cudaGetSymbolAddress((void**)&woh, g_woh);
    cudaGetSymbolAddress((void**)&wol, g_wol);
    cudaGetSymbolAddress((void**)&qkvh, g_qkvh);
    cudaGetSymbolAddress((void**)&qkvl, g_qkvl);

    float* out = (float*)d_out;
    const long OUT_E = (long)BSc * Dc;
    const long ATT_E = (long)Bc * Hc * Sc * Sc;
    float* attn = ((long)out_size >= OUT_E + ATT_E) ? (out + OUT_E) : attnscr;

    cudaFuncSetAttribute(mma_gemm_kernel,
                         cudaFuncAttributeMaxDynamicSharedMemorySize, GSMEM);
    cudaFuncSetAttribute(qk_mma_kernel,
                         cudaFuncAttributeMaxDynamicSharedMemorySize, QK_SMEM);
    cudaFuncSetAttribute(av_mma_kernel,
                         cudaFuncAttributeMaxDynamicSharedMemorySize, AV_SMEM);

    const int n4x = BSc * Dc / 4;
    split_kernel<<<(n4x + 255) / 256, 256>>>(x, ah, al, n4x);
    transpose_split_kernel<<<dim3(D3c / 32, Dc / 32), dim3(32, 8)>>>(qkv_w, wqh, wql, Dc, D3c);
    transpose_split_kernel<<<dim3(Dc / 32, Dc / 32), dim3(32, 8)>>>(out_w, woh, wol, Dc, Dc);

    // 1) qkv: emit bf16 hi/lo (q cols pre-scaled 1/8)
    mma_gemm_kernel<<<dim3(D3c / 128, BSc / 128), 256, GSMEM>>>(
        ah, al, wqh, wql, qkv_b, nullptr, qkvh, qkvl, 1, BSc, D3c, Dc);
    // 2) logits = (q/8) . k
    qk_mma_kernel<<<dim3(3, 3, Bc * Hc), 256, QK_SMEM>>>(qkvh, qkvl, attn);
    // 3+4) rpe bias (f32x2) + softmax
    rpe_softmax_kernel<<<Hc * Sc, 128>>>(qkvh, qkvl, rpe, attn);
    // 5) values = attn @ v -> bf16 hi/lo
    av_mma_kernel<<<dim3(3, Bc * Hc), 256, AV_SMEM>>>(attn, qkvh, qkvl, ah, al);
    // 6) out = values @ out_w + out_b
    mma_gemm_kernel<<<dim3(Dc / 128, BSc / 128), 256, GSMEM>>>(
        ah, al, woh, wol, out_b, out, nullptr, nullptr, 0, BSc, Dc, Dc);
}